// round 14
// baseline (speedup 1.0000x reference)
#include <cuda_runtime.h>
#include <cuda_bf16.h>
#include <cuda_fp16.h>
#include <math.h>
#include <stdint.h>

// ---------------- problem constants ----------------
#define BWIN   512
#define NTOK   144
#define CDIM   512
#define HEADS  16
#define DHEAD  32
#define NW     64
#define MROWS  (BWIN * NTOK)        // 73728
#define QKVC   (3 * CDIM)           // 1536
#define NPOS   (23 * 23)
#define CPBH   512

// ---------------- scratch ----------------
__device__ __half g_qh[(size_t)MROWS * CDIM];   // normalized*scale q, hi
__device__ __half g_ql[(size_t)MROWS * CDIM];   // q residual
__device__ __half g_kh[(size_t)MROWS * CDIM];   // normalized k, hi
__device__ __half g_kl[(size_t)MROWS * CDIM];   // k residual
__device__ __half g_vh[(size_t)MROWS * CDIM];   // v (fp16)
__device__ float  g_att [(size_t)MROWS * CDIM];
__device__ float  g_tbl [NPOS * HEADS];
__device__ float  g_bias[(size_t)HEADS * NTOK * NTOK];

__device__ __forceinline__ uint32_t s2u(const void* p) {
    return (uint32_t)__cvta_generic_to_shared(p);
}
__device__ __forceinline__ uint2 f4_to_h4(float4 v) {
    __half2 h0 = __float22half2_rn(make_float2(v.x, v.y));
    __half2 h1 = __float22half2_rn(make_float2(v.z, v.w));
    uint2 u;
    u.x = *(uint32_t*)&h0;
    u.y = *(uint32_t*)&h1;
    return u;
}
__device__ __forceinline__ void split_pack(float x, float y, uint32_t& hi, uint32_t& lo) {
    __half hx = __float2half_rn(x), hy = __float2half_rn(y);
    __half2 h = __halves2half2(hx, hy);
    hi = *(uint32_t*)&h;
    __half2 l = __floats2half2_rn(x - __half2float(hx), y - __half2float(hy));
    lo = *(uint32_t*)&l;
}
__device__ __forceinline__ uint32_t pack_h2(float x, float y) {
    __half2 h = __floats2half2_rn(x, y);
    return *(uint32_t*)&h;
}

#define MMA_F16(d, a0,a1,a2,a3, b0,b1)                                         \
    asm volatile("mma.sync.aligned.m16n8k16.row.col.f32.f16.f16.f32 "          \
                 "{%0,%1,%2,%3},{%4,%5,%6,%7},{%8,%9},{%0,%1,%2,%3};"          \
                 : "+f"(d[0]), "+f"(d[1]), "+f"(d[2]), "+f"(d[3])              \
                 : "r"(a0), "r"(a1), "r"(a2), "r"(a3), "r"(b0), "r"(b1))

#define LDSM_X4(r0,r1,r2,r3, addr)                                             \
    asm volatile("ldmatrix.sync.aligned.m8n8.x4.shared.b16 {%0,%1,%2,%3}, [%4];" \
                 : "=r"(r0), "=r"(r1), "=r"(r2), "=r"(r3) : "r"(addr))

// =========================================================================
// Shared GEMM config (proven mainloop)
// =========================================================================
#define GBK    32
#define GLDH   40
#define ABUFH  (128 * GLDH)
#define BBUFH  (256 * GLDH)
#define GT_SMEM_BYTES ((2 * ABUFH + 2 * BBUFH) * 2)   // 61440

#define GEMM_MAINLOOP_BODY(A_, B_, K_)                                          \
    extern __shared__ __align__(16) __half gsm[];                               \
    __half* As = gsm;                                                           \
    __half* Bs = gsm + 2 * ABUFH;                                               \
    const int tid  = threadIdx.x;                                               \
    const int lane = tid & 31;                                                  \
    const int warp = tid >> 5;                                                  \
    const int warpM = (warp & 3) * 32;                                          \
    const int warpN = (warp >> 2) * 64;                                         \
    const int rowBase = blockIdx.y * 128;                                       \
    const int colBase = blockIdx.x * 256;                                       \
    const int r  = tid >> 3;                                                    \
    const int kq = tid & 7;                                                     \
    const float* Ag = (A_) + (size_t)(rowBase + r) * (K_) + kq * 4;             \
    const float* Bg = (B_) + (size_t)(colBase + r) * (K_) + kq * 4;             \
    float4 ra[2], rb[4];                                                        \
    float acc[2][8][4];                                                         \
    _Pragma("unroll")                                                           \
    for (int mi = 0; mi < 2; mi++)                                              \
        _Pragma("unroll")                                                       \
        for (int ni = 0; ni < 8; ni++)                                          \
            _Pragma("unroll")                                                   \
            for (int c = 0; c < 4; c++) acc[mi][ni][c] = 0.f;                   \
    const uint32_t aOff = (uint32_t)((warpM + (lane & 7) + ((lane >> 3) & 1) * 8) * (GLDH * 2)) \
                        + (uint32_t)(lane >> 4) * 16;                           \
    const uint32_t bOff = (uint32_t)((warpN + (lane & 7) + ((lane & 16) ? 8 : 0)) * (GLDH * 2)) \
                        + (uint32_t)((lane >> 3) & 1) * 16;                     \
    const uint32_t asBase = s2u(As);                                            \
    const uint32_t bsBase = s2u(Bs);                                            \
    {                                                                           \
        const float* ap = Ag; const float* bp = Bg;                             \
        ra[0] = *(const float4*)(ap);                                           \
        ra[1] = *(const float4*)(ap + (size_t)64 * (K_));                       \
        rb[0] = *(const float4*)(bp);                                           \
        rb[1] = *(const float4*)(bp + (size_t)64 * (K_));                       \
        rb[2] = *(const float4*)(bp + (size_t)128 * (K_));                      \
        rb[3] = *(const float4*)(bp + (size_t)192 * (K_));                      \
        _Pragma("unroll")                                                       \
        for (int i = 0; i < 2; i++)                                             \
            *(uint2*)&As[(r + 64 * i) * GLDH + kq * 4] = f4_to_h4(ra[i]);       \
        _Pragma("unroll")                                                       \
        for (int i = 0; i < 4; i++)                                             \
            *(uint2*)&Bs[(r + 64 * i) * GLDH + kq * 4] = f4_to_h4(rb[i]);       \
    }                                                                           \
    __syncthreads();                                                            \
    const int NIT = (K_) / GBK;                                                 \
    for (int it = 0; it < NIT; ++it) {                                          \
        const int buf = it & 1;                                                 \
        if (it + 1 < NIT) {                                                     \
            const float* ap = Ag + (it + 1) * GBK;                              \
            const float* bp = Bg + (it + 1) * GBK;                              \
            ra[0] = *(const float4*)(ap);                                       \
            ra[1] = *(const float4*)(ap + (size_t)64 * (K_));                   \
            rb[0] = *(const float4*)(bp);                                       \
            rb[1] = *(const float4*)(bp + (size_t)64 * (K_));                   \
            rb[2] = *(const float4*)(bp + (size_t)128 * (K_));                  \
            rb[3] = *(const float4*)(bp + (size_t)192 * (K_));                  \
        }                                                                       \
        const uint32_t aB = asBase + (uint32_t)buf * (ABUFH * 2);               \
        const uint32_t bB = bsBase + (uint32_t)buf * (BBUFH * 2);               \
        _Pragma("unroll")                                                       \
        for (int kk = 0; kk < 2; kk++) {                                        \
            uint32_t a[2][4], bf[8][2];                                         \
            _Pragma("unroll")                                                   \
            for (int mi = 0; mi < 2; mi++) {                                    \
                uint32_t addr = aB + aOff + (uint32_t)(mi * 16 * GLDH * 2) + (uint32_t)(kk * 32); \
                LDSM_X4(a[mi][0], a[mi][1], a[mi][2], a[mi][3], addr);          \
            }                                                                   \
            _Pragma("unroll")                                                   \
            for (int p = 0; p < 4; p++) {                                       \
                uint32_t addr = bB + bOff + (uint32_t)(p * 16 * GLDH * 2) + (uint32_t)(kk * 32); \
                uint32_t r0, r1, r2, r3;                                        \
                LDSM_X4(r0, r1, r2, r3, addr);                                  \
                bf[2 * p][0] = r0; bf[2 * p][1] = r1;                           \
                bf[2 * p + 1][0] = r2; bf[2 * p + 1][1] = r3;                   \
            }                                                                   \
            _Pragma("unroll")                                                   \
            for (int mi = 0; mi < 2; mi++)                                      \
                _Pragma("unroll")                                               \
                for (int ni = 0; ni < 8; ni++)                                  \
                    MMA_F16(acc[mi][ni], a[mi][0], a[mi][1], a[mi][2], a[mi][3],\
                            bf[ni][0], bf[ni][1]);                              \
        }                                                                       \
        if (it + 1 < NIT) {                                                     \
            const int nb = buf ^ 1;                                             \
            _Pragma("unroll")                                                   \
            for (int i = 0; i < 2; i++)                                         \
                *(uint2*)&As[nb * ABUFH + (r + 64 * i) * GLDH + kq * 4] = f4_to_h4(ra[i]); \
            _Pragma("unroll")                                                   \
            for (int i = 0; i < 4; i++)                                         \
                *(uint2*)&Bs[nb * BBUFH + (r + 64 * i) * GLDH + kq * 4] = f4_to_h4(rb[i]); \
        }                                                                       \
        __syncthreads();                                                        \
    }

// =========================================================================
// QKV GEMM with fused normalize+split epilogue.
// Output cols: [0,512) Q -> qh/ql (normalized*scale, hi/lo fp16)
//              [512,1024) K -> kh/kl (normalized, hi/lo fp16)
//              [1024,1536) V -> vh (fp16)
// =========================================================================
__global__ __launch_bounds__(512, 1)
void gemm_qkv_fused(const float* __restrict__ A,
                    const float* __restrict__ B,
                    const float* __restrict__ logit_scale,
                    __half* __restrict__ qh, __half* __restrict__ ql,
                    __half* __restrict__ kh, __half* __restrict__ kl,
                    __half* __restrict__ vh)
{
    GEMM_MAINLOOP_BODY(A, B, CDIM)

    const int g  = lane >> 2;
    const int region = (colBase + warpN) >> 9;       // 0=Q,1=K,2=V
    const int colLoc = (colBase + warpN) & 511;      // local col base
    const int cq = (lane & 3) * 2;

    if (region == 2) {
        // V: plain fp16 store
#pragma unroll
        for (int mi = 0; mi < 2; mi++) {
            const size_t r0 = (size_t)(rowBase + warpM + mi * 16 + g);
#pragma unroll
            for (int ni = 0; ni < 8; ni++) {
                const int cl = colLoc + ni * 8 + cq;
                *(uint32_t*)&vh[r0 * CDIM + cl] =
                    pack_h2(acc[mi][ni][0], acc[mi][ni][1]);
                *(uint32_t*)&vh[(r0 + 8) * CDIM + cl] =
                    pack_h2(acc[mi][ni][2], acc[mi][ni][3]);
            }
        }
        return;
    }

    __half* hiB = (region == 0) ? qh : kh;
    __half* loB = (region == 0) ? ql : kl;
    float gscale[2] = {1.f, 1.f};
    if (region == 0) {
#pragma unroll
        for (int grp = 0; grp < 2; grp++) {
            int head = (colLoc >> 5) + grp;
            gscale[grp] = __expf(fminf(logit_scale[head], 4.60517018598809f));
        }
    }

#pragma unroll
    for (int mi = 0; mi < 2; mi++) {
        const size_t r0 = (size_t)(rowBase + warpM + mi * 16 + g);
#pragma unroll
        for (int grp = 0; grp < 2; grp++) {
            float s0 = 0.f, s1 = 0.f;
#pragma unroll
            for (int ni = 4 * grp; ni < 4 * grp + 4; ni++) {
                s0 += acc[mi][ni][0] * acc[mi][ni][0] + acc[mi][ni][1] * acc[mi][ni][1];
                s1 += acc[mi][ni][2] * acc[mi][ni][2] + acc[mi][ni][3] * acc[mi][ni][3];
            }
            s0 += __shfl_xor_sync(0xffffffffu, s0, 1);
            s0 += __shfl_xor_sync(0xffffffffu, s0, 2);
            s1 += __shfl_xor_sync(0xffffffffu, s1, 1);
            s1 += __shfl_xor_sync(0xffffffffu, s1, 2);
            float rn0 = rsqrtf(s0) * gscale[grp];
            float rn1 = rsqrtf(s1) * gscale[grp];
#pragma unroll
            for (int ni = 4 * grp; ni < 4 * grp + 4; ni++) {
                const int cl = colLoc + ni * 8 + cq;
                uint32_t hi, lo;
                split_pack(acc[mi][ni][0] * rn0, acc[mi][ni][1] * rn0, hi, lo);
                *(uint32_t*)&hiB[r0 * CDIM + cl] = hi;
                *(uint32_t*)&loB[r0 * CDIM + cl] = lo;
                split_pack(acc[mi][ni][2] * rn1, acc[mi][ni][3] * rn1, hi, lo);
                *(uint32_t*)&hiB[(r0 + 8) * CDIM + cl] = hi;
                *(uint32_t*)&loB[(r0 + 8) * CDIM + cl] = lo;
            }
        }
    }
}

// =========================================================================
// Output-projection GEMM (fp32 in, +bias) — unchanged proven kernel
// =========================================================================
__global__ __launch_bounds__(512, 1)
void gemm_proj(const float* __restrict__ A,
               const float* __restrict__ B,
               const float* __restrict__ bias,
               float* __restrict__ C)
{
    GEMM_MAINLOOP_BODY(A, B, CDIM)

    const int g  = lane >> 2;
    const int cq = (lane & 3) * 2;
#pragma unroll
    for (int mi = 0; mi < 2; mi++) {
        const int row0 = rowBase + warpM + mi * 16 + g;
#pragma unroll
        for (int ni = 0; ni < 8; ni++) {
            const int col = colBase + warpN + ni * 8 + cq;
            float b0 = bias[col], b1 = bias[col + 1];
            *(float2*)&C[(size_t)row0 * CDIM + col] =
                make_float2(acc[mi][ni][0] + b0, acc[mi][ni][1] + b1);
            *(float2*)&C[(size_t)(row0 + 8) * CDIM + col] =
                make_float2(acc[mi][ni][2] + b0, acc[mi][ni][3] + b1);
        }
    }
}

// =========================================================================
// CPB MLP table + bias gather (tiny, unchanged)
// =========================================================================
__global__ __launch_bounds__(512)
void cpb_tbl_kernel(const float* __restrict__ rel_table,
                    const float* __restrict__ w1,
                    const float* __restrict__ b1,
                    const float* __restrict__ w2,
                    float* __restrict__ tbl)
{
    __shared__ float hid[CPBH];
    int p = blockIdx.x;
    float t0 = rel_table[2 * p], t1 = rel_table[2 * p + 1];
    int j = threadIdx.x;
    hid[j] = fmaxf(t0 * w1[2 * j] + t1 * w1[2 * j + 1] + b1[j], 0.f);
    __syncthreads();

    int warp = j >> 5, lane = j & 31;
    const float* w2h = w2 + warp * CPBH;
    float s = 0.f;
#pragma unroll
    for (int q = lane; q < CPBH; q += 32) s += hid[q] * w2h[q];
#pragma unroll
    for (int o = 16; o > 0; o >>= 1) s += __shfl_xor_sync(0xffffffffu, s, o);
    if (lane == 0) tbl[p * HEADS + warp] = s;
}

__global__ void bias_gather_kernel(const float* __restrict__ tbl,
                                   const int* __restrict__ rel_index,
                                   float* __restrict__ bias)
{
    int t = blockIdx.x * blockDim.x + threadIdx.x;
    const int TOT = HEADS * NTOK * NTOK;
    if (t >= TOT) return;
    int h  = t / (NTOK * NTOK);
    int ij = t % (NTOK * NTOK);
    float x = tbl[rel_index[ij] * HEADS + h];
    bias[(size_t)h * NTOK * NTOK + ij] = 16.f / (1.f + __expf(-x));
}

// =========================================================================
// Window attention v8: inputs pre-normalized/pre-split fp16 from the fused
// QKV epilogue. Pre-phase = pure loads+stores. QK split-fp16 (3 terms),
// PV plain fp16. 18 warps / CTA.
// =========================================================================
#define KSTR_H 40
#define VSTR_H 152
#define PVSTR  18

#define AK_KHI 0
#define AK_KLO (AK_KHI + NTOK * KSTR_H * 2)
#define AK_VHI (AK_KLO + NTOK * KSTR_H * 2)
#define AK_PVB (AK_VHI + DHEAD * VSTR_H * 2)
#define AK_SUM (AK_PVB + 9 * 32 * PVSTR * 4)
#define ATTN_SMEM_BYTES (AK_SUM + 9 * 2 * 32 * 4)

__global__ __launch_bounds__(576, 1)
void attn_tc8_kernel(const __half* __restrict__ qh, const __half* __restrict__ ql,
                     const __half* __restrict__ kh, const __half* __restrict__ kl,
                     const __half* __restrict__ vh,
                     const float* __restrict__ bias,
                     const float* __restrict__ mask,
                     float* __restrict__ out)
{
    extern __shared__ __align__(16) char dsm[];

    const int h = blockIdx.x;
    const int b = blockIdx.y;
    const int w = b & (NW - 1);

    const int tid  = threadIdx.x;
    const int lane = tid & 31;
    const int warp = tid >> 5;
    const int pair = warp % 9;
    const int half = warp / 9;
    const int ng   = half ? 5 : 4;
    const int hbase = half ? 64 : 0;
    const int g  = lane >> 2;
    const int t  = lane & 3;
    const int R0 = pair * 16;

    const size_t rowB = (size_t)b * NTOK;
    const size_t hOff = (size_t)h * DHEAD;

    __half* knHi = (__half*)(dsm + AK_KHI);
    __half* knLo = (__half*)(dsm + AK_KLO);
    __half* vtHi = (__half*)(dsm + AK_VHI);
    float*  pvb  = (float*)(dsm + AK_PVB);
    float*  sumb = (float*)(dsm + AK_SUM);
    const uint32_t knHiB = s2u(knHi);
    const uint32_t knLoB = s2u(knLo);
    const uint32_t vtHiB = s2u(vtHi);

    // ---------- PHASE 0: front-batched loads ----------
    __half khr[8], klr[8], vhr[8];
#pragma unroll
    for (int i = 0; i < 8; i++) {
        int j = warp * 8 + i;
        khr[i] = kh[(rowB + j) * CDIM + hOff + lane];
        klr[i] = kl[(rowB + j) * CDIM + hOff + lane];
        vhr[i] = vh[(rowB + j) * CDIM + hOff + lane];
    }
    uint32_t qah[2][4], qal[2][4];
    {
        const __half* qh0 = qh + (rowB + R0 + g) * CDIM + hOff;
        const __half* qh1 = qh0 + 8 * CDIM;
        const __half* ql0 = ql + (rowB + R0 + g) * CDIM + hOff;
        const __half* ql1 = ql0 + 8 * CDIM;
#pragma unroll
        for (int kc = 0; kc < 2; kc++) {
            qah[kc][0] = *(const uint32_t*)(qh0 + 16 * kc + 2 * t);
            qah[kc][1] = *(const uint32_t*)(qh1 + 16 * kc + 2 * t);
            qah[kc][2] = *(const uint32_t*)(qh0 + 16 * kc + 8 + 2 * t);
            qah[kc][3] = *(const uint32_t*)(qh1 + 16 * kc + 8 + 2 * t);
            qal[kc][0] = *(const uint32_t*)(ql0 + 16 * kc + 2 * t);
            qal[kc][1] = *(const uint32_t*)(ql1 + 16 * kc + 2 * t);
            qal[kc][2] = *(const uint32_t*)(ql0 + 16 * kc + 8 + 2 * t);
            qal[kc][3] = *(const uint32_t*)(ql1 + 16 * kc + 8 + 2 * t);
        }
    }
    float acc[10][4];
    {
        const float* biasR0 = bias + (size_t)h * NTOK * NTOK + (size_t)(R0 + g) * NTOK + hbase + 2 * t;
        const float* biasR1 = biasR0 + 8 * NTOK;
        const float* maskR0 = mask + (size_t)w * NTOK * NTOK + (size_t)(R0 + g) * NTOK + hbase + 2 * t;
        const float* maskR1 = maskR0 + 8 * NTOK;
#pragma unroll
        for (int nt = 0; nt < 10; nt++) {
            if (nt < 2 * ng) {
                float2 bb0 = *(const float2*)(biasR0 + 8 * nt);
                float2 mm0 = *(const float2*)(maskR0 + 8 * nt);
                float2 bb1 = *(const float2*)(biasR1 + 8 * nt);
                float2 mm1 = *(const float2*)(maskR1 + 8 * nt);
                acc[nt][0] = bb0.x + mm0.x;
                acc[nt][1] = bb0.y + mm0.y;
                acc[nt][2] = bb1.x + mm1.x;
                acc[nt][3] = bb1.y + mm1.y;
            } else {
#pragma unroll
                for (int c = 0; c < 4; c++) acc[nt][c] = 0.f;
            }
        }
    }

    // ---------- PHASE 1: plain stores to smem ----------
#pragma unroll
    for (int i = 0; i < 8; i++) {
        int j = warp * 8 + i;
        knHi[j * KSTR_H + lane] = khr[i];
        knLo[j * KSTR_H + lane] = klr[i];
        vtHi[lane * VSTR_H + j] = vhr[i];
    }
    __syncthreads();

    // ---------- QK^T (split fp16, 3 terms) onto bias+mask ----------
    const uint32_t ldsmRow = (uint32_t)((lane & 7) + ((lane & 16) ? 8 : 0));
    const uint32_t ldsmCol = (uint32_t)((lane >> 3) & 1) * 16;

#pragma unroll
    for (int kc = 0; kc < 2; kc++) {
#pragma unroll
        for (int gI = 0; gI < 5; gI++) {
            if (gI < ng) {
                uint32_t off = (uint32_t)(hbase + gI * 16 + ldsmRow) * (KSTR_H * 2)
                             + ldsmCol + (uint32_t)kc * 32;
                uint32_t bh0, bh1, bh2, bh3, bl0, bl1, bl2, bl3;
                LDSM_X4(bh0, bh1, bh2, bh3, knHiB + off);
                LDSM_X4(bl0, bl1, bl2, bl3, knLoB + off);
                MMA_F16(acc[2 * gI],     qah[kc][0], qah[kc][1], qah[kc][2], qah[kc][3], bh0, bh1);
                MMA_F16(acc[2 * gI],     qah[kc][0], qah[kc][1], qah[kc][2], qah[kc][3], bl0, bl1);
                MMA_F16(acc[2 * gI],     qal[kc][0], qal[kc][1], qal[kc][2], qal[kc][3], bh0, bh1);
                MMA_F16(acc[2 * gI + 1], qah[kc][0], qah[kc][1], qah[kc][2], qah[kc][3], bh2, bh3);
                MMA_F16(acc[2 * gI + 1], qah[kc][0], qah[kc][1], qah[kc][2], qah[kc][3], bl2, bl3);
                MMA_F16(acc[2 * gI + 1], qal[kc][0], qal[kc][1], qal[kc][2], qal[kc][3], bh2, bh3);
            }
        }
    }

    // ---------- local max, exp, local sums ----------
    float mx0 = -1e30f, mx1 = -1e30f, sm0 = 0.f, sm1 = 0.f;
    {
#pragma unroll
        for (int nt = 0; nt < 10; nt++) {
            if (nt < 2 * ng) {
                mx0 = fmaxf(mx0, fmaxf(acc[nt][0], acc[nt][1]));
                mx1 = fmaxf(mx1, fmaxf(acc[nt][2], acc[nt][3]));
            }
        }
        mx0 = fmaxf(mx0, __shfl_xor_sync(0xffffffffu, mx0, 1));
        mx0 = fmaxf(mx0, __shfl_xor_sync(0xffffffffu, mx0, 2));
        mx1 = fmaxf(mx1, __shfl_xor_sync(0xffffffffu, mx1, 1));
        mx1 = fmaxf(mx1, __shfl_xor_sync(0xffffffffu, mx1, 2));
#pragma unroll
        for (int nt = 0; nt < 10; nt++) {
            if (nt < 2 * ng) {
                acc[nt][0] = __expf(acc[nt][0] - mx0);
                acc[nt][1] = __expf(acc[nt][1] - mx0);
                acc[nt][2] = __expf(acc[nt][2] - mx1);
                acc[nt][3] = __expf(acc[nt][3] - mx1);
                sm0 += acc[nt][0] + acc[nt][1];
                sm1 += acc[nt][2] + acc[nt][3];
            }
        }
        sm0 += __shfl_xor_sync(0xffffffffu, sm0, 1);
        sm0 += __shfl_xor_sync(0xffffffffu, sm0, 2);
        sm1 += __shfl_xor_sync(0xffffffffu, sm1, 1);
        sm1 += __shfl_xor_sync(0xffffffffu, sm1, 2);
        if (t == 0) {
            float* sb = sumb + (pair * 2 + half) * 32;
            sb[g]          = sm0;
            sb[g + 8]      = sm1;
            sb[16 + g]     = mx0;
            sb[16 + g + 8] = mx1;
        }
    }

    // ---------- PV (plain fp16) ----------
    float pv[4][4];
#pragma unroll
    for (int nt = 0; nt < 4; nt++)
#pragma unroll
        for (int c = 0; c < 4; c++) pv[nt][c] = 0.f;

#pragma unroll
    for (int kc2 = 0; kc2 < 5; kc2++) {
        if (kc2 < ng) {
            uint32_t ph[4];
            ph[0] = pack_h2(acc[2 * kc2][0],     acc[2 * kc2][1]);
            ph[1] = pack_h2(acc[2 * kc2][2],     acc[2 * kc2][3]);
            ph[2] = pack_h2(acc[2 * kc2 + 1][0], acc[2 * kc2 + 1][1]);
            ph[3] = pack_h2(acc[2 * kc2 + 1][2], acc[2 * kc2 + 1][3]);
            const uint32_t gk = (uint32_t)((hbase >> 4) + kc2);
#pragma unroll
            for (int p = 0; p < 2; p++) {
                uint32_t off = (uint32_t)(p * 16 + ldsmRow) * (VSTR_H * 2)
                             + ldsmCol + gk * 32;
                uint32_t bh0, bh1, bh2, bh3;
                LDSM_X4(bh0, bh1, bh2, bh3, vtHiB + off);
                MMA_F16(pv[2 * p],     ph[0], ph[1], ph[2], ph[3], bh0, bh1);
                MMA_F16(pv[2 * p + 1], ph[0], ph[1], ph[2], ph[3], bh2, bh3);
            }
        }
    }

    // ---------- pairwise combine (max-corrected) + epilogue ----------
    if (half == 1) {
        float* pb = pvb + (pair * 32 + lane) * PVSTR;
#pragma unroll
        for (int nt = 0; nt < 4; nt++) {
            *(float2*)(pb + nt * 4)     = make_float2(pv[nt][0], pv[nt][1]);
            *(float2*)(pb + nt * 4 + 2) = make_float2(pv[nt][2], pv[nt][3]);
        }
    }
    __syncthreads();
    if (half == 0) {
        const float* sbO = sumb + (pair * 2 + 1) * 32;
        const float smO0 = sbO[g],      mxO0 = sbO[16 + g];
        const float smO1 = sbO[g + 8],  mxO1 = sbO[16 + g + 8];
        const float M0 = fmaxf(mx0, mxO0);
        const float M1 = fmaxf(mx1, mxO1);
        const float fl0 = __expf(mx0 - M0), fo0 = __expf(mxO0 - M0);
        const float fl1 = __expf(mx1 - M1), fo1 = __expf(mxO1 - M1);
        const float inv0 = 1.f / (sm0 * fl0 + smO0 * fo0);
        const float inv1 = 1.f / (sm1 * fl1 + smO1 * fo1);
        const float* pb = pvb + (pair * 32 + lane) * PVSTR;
        float* o0 = out + (rowB + R0 + g) * CDIM + hOff + 2 * t;
        float* o1 = o0 + (size_t)8 * CDIM;
#pragma unroll
        for (int nt = 0; nt < 4; nt++) {
            float2 q0 = *(const float2*)(pb + nt * 4);
            float2 q1 = *(const float2*)(pb + nt * 4 + 2);
            *(float2*)(o0 + 8 * nt) = make_float2((pv[nt][0] * fl0 + q0.x * fo0) * inv0,
                                                  (pv[nt][1] * fl0 + q0.y * fo0) * inv0);
            *(float2*)(o1 + 8 * nt) = make_float2((pv[nt][2] * fl1 + q1.x * fo1) * inv1,
                                                  (pv[nt][3] * fl1 + q1.y * fo1) * inv1);
        }
    }
}

// =========================================================================
// launch
// =========================================================================
extern "C" void kernel_launch(void* const* d_in, const int* in_sizes, int n_in,
                              void* d_out, int out_size)
{
    const float* x           = (const float*)d_in[0];
    const float* mask        = (const float*)d_in[1];
    const float* qkv_w       = (const float*)d_in[2];
    const float* logit_scale = (const float*)d_in[3];
    const float* cpb_w1      = (const float*)d_in[4];
    const float* cpb_b1      = (const float*)d_in[5];
    const float* cpb_w2      = (const float*)d_in[6];
    const float* proj_w      = (const float*)d_in[7];
    const float* proj_b      = (const float*)d_in[8];
    const float* rel_table   = (const float*)d_in[9];
    const int*   rel_index   = (const int*)d_in[10];
    float* out = (float*)d_out;

    __half *qh, *ql, *kh, *kl, *vh;
    float *att, *tbl, *bias;
    cudaGetSymbolAddress((void**)&qh,   g_qh);
    cudaGetSymbolAddress((void**)&ql,   g_ql);
    cudaGetSymbolAddress((void**)&kh,   g_kh);
    cudaGetSymbolAddress((void**)&kl,   g_kl);
    cudaGetSymbolAddress((void**)&vh,   g_vh);
    cudaGetSymbolAddress((void**)&att,  g_att);
    cudaGetSymbolAddress((void**)&tbl,  g_tbl);
    cudaGetSymbolAddress((void**)&bias, g_bias);

    cudaFuncSetAttribute(gemm_qkv_fused,
                         cudaFuncAttributeMaxDynamicSharedMemorySize, GT_SMEM_BYTES);
    cudaFuncSetAttribute(gemm_proj,
                         cudaFuncAttributeMaxDynamicSharedMemorySize, GT_SMEM_BYTES);
    cudaFuncSetAttribute(attn_tc8_kernel,
                         cudaFuncAttributeMaxDynamicSharedMemorySize, ATTN_SMEM_BYTES);

    // 1) QKV projection + fused normalize/split epilogue
    {
        dim3 grid(QKVC / 256, MROWS / 128);
        gemm_qkv_fused<<<grid, 512, GT_SMEM_BYTES>>>(x, qkv_w, logit_scale,
                                                     qh, ql, kh, kl, vh);
    }

    // 2) relative position bias table + gather
    cpb_tbl_kernel<<<NPOS, CPBH>>>(rel_table, cpb_w1, cpb_b1, cpb_w2, tbl);
    {
        int tot = HEADS * NTOK * NTOK;
        bias_gather_kernel<<<(tot + 255) / 256, 256>>>(tbl, rel_index, bias);
    }

    // 3) attention v8 (pre-normalized fp16 inputs)
    {
        dim3 grid(HEADS, BWIN);
        attn_tc8_kernel<<<grid, 576, ATTN_SMEM_BYTES>>>(qh, ql, kh, kl, vh,
                                                        bias, mask, att);
    }

    // 4) output projection
    {
        dim3 grid(CDIM / 256, MROWS / 128);
        gemm_proj<<<grid, 512, GT_SMEM_BYTES>>>(att, proj_w, proj_b, out);
    }
}

// round 15
// speedup vs baseline: 1.1221x; 1.1221x over previous
#include <cuda_runtime.h>
#include <cuda_bf16.h>
#include <cuda_fp16.h>
#include <math.h>
#include <stdint.h>

// ---------------- problem constants ----------------
#define BWIN   512
#define NTOK   144
#define CDIM   512
#define HEADS  16
#define DHEAD  32
#define NW     64
#define MROWS  (BWIN * NTOK)        // 73728
#define QKVC   (3 * CDIM)           // 1536
#define NPOS   (23 * 23)
#define CPBH   512

// ---------------- scratch ----------------
// q/k: interleaved (hi_pair, lo_pair) per column pair -> coalesced 8B stores
__device__ uint2  g_qs[(size_t)MROWS * (CDIM / 2)];
__device__ uint2  g_ks[(size_t)MROWS * (CDIM / 2)];
__device__ __half g_vh[(size_t)MROWS * CDIM];
__device__ __half g_attH[(size_t)MROWS * CDIM];
__device__ float  g_tbl [NPOS * HEADS];
__device__ float  g_bias[(size_t)HEADS * NTOK * NTOK];

__device__ __forceinline__ uint32_t s2u(const void* p) {
    return (uint32_t)__cvta_generic_to_shared(p);
}
__device__ __forceinline__ uint2 f4_to_h4(float4 v) {
    __half2 h0 = __float22half2_rn(make_float2(v.x, v.y));
    __half2 h1 = __float22half2_rn(make_float2(v.z, v.w));
    uint2 u;
    u.x = *(uint32_t*)&h0;
    u.y = *(uint32_t*)&h1;
    return u;
}
__device__ __forceinline__ void split_pack(float x, float y, uint32_t& hi, uint32_t& lo) {
    __half hx = __float2half_rn(x), hy = __float2half_rn(y);
    __half2 h = __halves2half2(hx, hy);
    hi = *(uint32_t*)&h;
    __half2 l = __floats2half2_rn(x - __half2float(hx), y - __half2float(hy));
    lo = *(uint32_t*)&l;
}
__device__ __forceinline__ uint32_t pack_h2(float x, float y) {
    __half2 h = __floats2half2_rn(x, y);
    return *(uint32_t*)&h;
}

#define MMA_F16(d, a0,a1,a2,a3, b0,b1)                                         \
    asm volatile("mma.sync.aligned.m16n8k16.row.col.f32.f16.f16.f32 "          \
                 "{%0,%1,%2,%3},{%4,%5,%6,%7},{%8,%9},{%0,%1,%2,%3};"          \
                 : "+f"(d[0]), "+f"(d[1]), "+f"(d[2]), "+f"(d[3])              \
                 : "r"(a0), "r"(a1), "r"(a2), "r"(a3), "r"(b0), "r"(b1))

#define LDSM_X4(r0,r1,r2,r3, addr)                                             \
    asm volatile("ldmatrix.sync.aligned.m8n8.x4.shared.b16 {%0,%1,%2,%3}, [%4];" \
                 : "=r"(r0), "=r"(r1), "=r"(r2), "=r"(r3) : "r"(addr))

// =========================================================================
// Shared GEMM config (proven mainloop, fp32 A + fp32 B)
// =========================================================================
#define GBK    32
#define GLDH   40
#define ABUFH  (128 * GLDH)
#define BBUFH  (256 * GLDH)
#define GT_SMEM_BYTES ((2 * ABUFH + 2 * BBUFH) * 2)   // 61440

#define GEMM_MAINLOOP_BODY(A_, B_, K_)                                          \
    extern __shared__ __align__(16) __half gsm[];                               \
    __half* As = gsm;                                                           \
    __half* Bs = gsm + 2 * ABUFH;                                               \
    const int tid  = threadIdx.x;                                               \
    const int lane = tid & 31;                                                  \
    const int warp = tid >> 5;                                                  \
    const int warpM = (warp & 3) * 32;                                          \
    const int warpN = (warp >> 2) * 64;                                         \
    const int rowBase = blockIdx.y * 128;                                       \
    const int colBase = blockIdx.x * 256;                                       \
    const int r  = tid >> 3;                                                    \
    const int kq = tid & 7;                                                     \
    const float* Ag = (A_) + (size_t)(rowBase + r) * (K_) + kq * 4;             \
    const float* Bg = (B_) + (size_t)(colBase + r) * (K_) + kq * 4;             \
    float4 ra[2], rb[4];                                                        \
    float acc[2][8][4];                                                         \
    _Pragma("unroll")                                                           \
    for (int mi = 0; mi < 2; mi++)                                              \
        _Pragma("unroll")                                                       \
        for (int ni = 0; ni < 8; ni++)                                          \
            _Pragma("unroll")                                                   \
            for (int c = 0; c < 4; c++) acc[mi][ni][c] = 0.f;                   \
    const uint32_t aOff = (uint32_t)((warpM + (lane & 7) + ((lane >> 3) & 1) * 8) * (GLDH * 2)) \
                        + (uint32_t)(lane >> 4) * 16;                           \
    const uint32_t bOff = (uint32_t)((warpN + (lane & 7) + ((lane & 16) ? 8 : 0)) * (GLDH * 2)) \
                        + (uint32_t)((lane >> 3) & 1) * 16;                     \
    const uint32_t asBase = s2u(As);                                            \
    const uint32_t bsBase = s2u(Bs);                                            \
    {                                                                           \
        const float* ap = Ag; const float* bp = Bg;                             \
        ra[0] = *(const float4*)(ap);                                           \
        ra[1] = *(const float4*)(ap + (size_t)64 * (K_));                       \
        rb[0] = *(const float4*)(bp);                                           \
        rb[1] = *(const float4*)(bp + (size_t)64 * (K_));                       \
        rb[2] = *(const float4*)(bp + (size_t)128 * (K_));                      \
        rb[3] = *(const float4*)(bp + (size_t)192 * (K_));                      \
        _Pragma("unroll")                                                       \
        for (int i = 0; i < 2; i++)                                             \
            *(uint2*)&As[(r + 64 * i) * GLDH + kq * 4] = f4_to_h4(ra[i]);       \
        _Pragma("unroll")                                                       \
        for (int i = 0; i < 4; i++)                                             \
            *(uint2*)&Bs[(r + 64 * i) * GLDH + kq * 4] = f4_to_h4(rb[i]);       \
    }                                                                           \
    __syncthreads();                                                            \
    const int NIT = (K_) / GBK;                                                 \
    for (int it = 0; it < NIT; ++it) {                                          \
        const int buf = it & 1;                                                 \
        if (it + 1 < NIT) {                                                     \
            const float* ap = Ag + (it + 1) * GBK;                              \
            const float* bp = Bg + (it + 1) * GBK;                              \
            ra[0] = *(const float4*)(ap);                                       \
            ra[1] = *(const float4*)(ap + (size_t)64 * (K_));                   \
            rb[0] = *(const float4*)(bp);                                       \
            rb[1] = *(const float4*)(bp + (size_t)64 * (K_));                   \
            rb[2] = *(const float4*)(bp + (size_t)128 * (K_));                  \
            rb[3] = *(const float4*)(bp + (size_t)192 * (K_));                  \
        }                                                                       \
        const uint32_t aB = asBase + (uint32_t)buf * (ABUFH * 2);               \
        const uint32_t bB = bsBase + (uint32_t)buf * (BBUFH * 2);               \
        _Pragma("unroll")                                                       \
        for (int kk = 0; kk < 2; kk++) {                                        \
            uint32_t a[2][4], bf[8][2];                                         \
            _Pragma("unroll")                                                   \
            for (int mi = 0; mi < 2; mi++) {                                    \
                uint32_t addr = aB + aOff + (uint32_t)(mi * 16 * GLDH * 2) + (uint32_t)(kk * 32); \
                LDSM_X4(a[mi][0], a[mi][1], a[mi][2], a[mi][3], addr);          \
            }                                                                   \
            _Pragma("unroll")                                                   \
            for (int p = 0; p < 4; p++) {                                       \
                uint32_t addr = bB + bOff + (uint32_t)(p * 16 * GLDH * 2) + (uint32_t)(kk * 32); \
                uint32_t r0, r1, r2, r3;                                        \
                LDSM_X4(r0, r1, r2, r3, addr);                                  \
                bf[2 * p][0] = r0; bf[2 * p][1] = r1;                           \
                bf[2 * p + 1][0] = r2; bf[2 * p + 1][1] = r3;                   \
            }                                                                   \
            _Pragma("unroll")                                                   \
            for (int mi = 0; mi < 2; mi++)                                      \
                _Pragma("unroll")                                               \
                for (int ni = 0; ni < 8; ni++)                                  \
                    MMA_F16(acc[mi][ni], a[mi][0], a[mi][1], a[mi][2], a[mi][3],\
                            bf[ni][0], bf[ni][1]);                              \
        }                                                                       \
        if (it + 1 < NIT) {                                                     \
            const int nb = buf ^ 1;                                             \
            _Pragma("unroll")                                                   \
            for (int i = 0; i < 2; i++)                                         \
                *(uint2*)&As[nb * ABUFH + (r + 64 * i) * GLDH + kq * 4] = f4_to_h4(ra[i]); \
            _Pragma("unroll")                                                   \
            for (int i = 0; i < 4; i++)                                         \
                *(uint2*)&Bs[nb * BBUFH + (r + 64 * i) * GLDH + kq * 4] = f4_to_h4(rb[i]); \
        }                                                                       \
        __syncthreads();                                                        \
    }

// =========================================================================
// QKV GEMM with fused normalize+split epilogue (interleaved hi/lo stores).
// =========================================================================
__global__ __launch_bounds__(512, 1)
void gemm_qkv_fused(const float* __restrict__ A,
                    const float* __restrict__ B,
                    const float* __restrict__ logit_scale,
                    uint2* __restrict__ qs, uint2* __restrict__ ks,
                    __half* __restrict__ vh)
{
    GEMM_MAINLOOP_BODY(A, B, CDIM)

    const int g  = lane >> 2;
    const int region = (colBase + warpN) >> 9;       // 0=Q,1=K,2=V
    const int colLoc = (colBase + warpN) & 511;
    const int cq = (lane & 3) * 2;

    if (region == 2) {
#pragma unroll
        for (int mi = 0; mi < 2; mi++) {
            const size_t r0 = (size_t)(rowBase + warpM + mi * 16 + g);
#pragma unroll
            for (int ni = 0; ni < 8; ni++) {
                const int cl = colLoc + ni * 8 + cq;
                *(uint32_t*)&vh[r0 * CDIM + cl] =
                    pack_h2(acc[mi][ni][0], acc[mi][ni][1]);
                *(uint32_t*)&vh[(r0 + 8) * CDIM + cl] =
                    pack_h2(acc[mi][ni][2], acc[mi][ni][3]);
            }
        }
        return;
    }

    uint2* dst = (region == 0) ? qs : ks;
    float gscale[2] = {1.f, 1.f};
    if (region == 0) {
#pragma unroll
        for (int grp = 0; grp < 2; grp++) {
            int head = (colLoc >> 5) + grp;
            gscale[grp] = __expf(fminf(logit_scale[head], 4.60517018598809f));
        }
    }

#pragma unroll
    for (int mi = 0; mi < 2; mi++) {
        const size_t r0 = (size_t)(rowBase + warpM + mi * 16 + g);
#pragma unroll
        for (int grp = 0; grp < 2; grp++) {
            float s0 = 0.f, s1 = 0.f;
#pragma unroll
            for (int ni = 4 * grp; ni < 4 * grp + 4; ni++) {
                s0 += acc[mi][ni][0] * acc[mi][ni][0] + acc[mi][ni][1] * acc[mi][ni][1];
                s1 += acc[mi][ni][2] * acc[mi][ni][2] + acc[mi][ni][3] * acc[mi][ni][3];
            }
            s0 += __shfl_xor_sync(0xffffffffu, s0, 1);
            s0 += __shfl_xor_sync(0xffffffffu, s0, 2);
            s1 += __shfl_xor_sync(0xffffffffu, s1, 1);
            s1 += __shfl_xor_sync(0xffffffffu, s1, 2);
            float rn0 = rsqrtf(s0) * gscale[grp];
            float rn1 = rsqrtf(s1) * gscale[grp];
#pragma unroll
            for (int ni = 4 * grp; ni < 4 * grp + 4; ni++) {
                const int pr = (colLoc + ni * 8 + cq) >> 1;   // column pair
                uint32_t hi, lo;
                split_pack(acc[mi][ni][0] * rn0, acc[mi][ni][1] * rn0, hi, lo);
                dst[r0 * (CDIM / 2) + pr] = make_uint2(hi, lo);
                split_pack(acc[mi][ni][2] * rn1, acc[mi][ni][3] * rn1, hi, lo);
                dst[(r0 + 8) * (CDIM / 2) + pr] = make_uint2(hi, lo);
            }
        }
    }
}

// =========================================================================
// Output projection: A = fp16 attention output (direct STS, no cvt), B fp32.
// =========================================================================
__global__ __launch_bounds__(512, 1)
void gemm_proj(const __half* __restrict__ A,
               const float* __restrict__ B,
               const float* __restrict__ bias,
               float* __restrict__ C)
{
    extern __shared__ __align__(16) __half gsm[];
    __half* As = gsm;
    __half* Bs = gsm + 2 * ABUFH;

    const int tid  = threadIdx.x;
    const int lane = tid & 31;
    const int warp = tid >> 5;
    const int warpM = (warp & 3) * 32;
    const int warpN = (warp >> 2) * 64;
    const int rowBase = blockIdx.y * 128;
    const int colBase = blockIdx.x * 256;

    const int r  = tid >> 3;
    const int kq = tid & 7;
    const __half* Ag = A + (size_t)(rowBase + r) * CDIM + kq * 4;
    const float*  Bg = B + (size_t)(colBase + r) * CDIM + kq * 4;

    uint2 ra[2];
    float4 rb[4];

    float acc[2][8][4];
#pragma unroll
    for (int mi = 0; mi < 2; mi++)
#pragma unroll
        for (int ni = 0; ni < 8; ni++)
#pragma unroll
            for (int c = 0; c < 4; c++) acc[mi][ni][c] = 0.f;

    const uint32_t aOff = (uint32_t)((warpM + (lane & 7) + ((lane >> 3) & 1) * 8) * (GLDH * 2))
                        + (uint32_t)(lane >> 4) * 16;
    const uint32_t bOff = (uint32_t)((warpN + (lane & 7) + ((lane & 16) ? 8 : 0)) * (GLDH * 2))
                        + (uint32_t)((lane >> 3) & 1) * 16;
    const uint32_t asBase = s2u(As);
    const uint32_t bsBase = s2u(Bs);

#define P_LOAD(it)  {                                                \
        const __half* ap = Ag + (it) * GBK;                          \
        const float*  bp = Bg + (it) * GBK;                          \
        ra[0] = *(const uint2*)(ap);                                 \
        ra[1] = *(const uint2*)(ap + (size_t)64 * CDIM);             \
        rb[0] = *(const float4*)(bp);                                \
        rb[1] = *(const float4*)(bp + (size_t)64 * CDIM);            \
        rb[2] = *(const float4*)(bp + (size_t)128 * CDIM);           \
        rb[3] = *(const float4*)(bp + (size_t)192 * CDIM);           \
    }
#define P_STS(buf)  {                                                           \
        _Pragma("unroll")                                                       \
        for (int i = 0; i < 2; i++)                                             \
            *(uint2*)&As[(buf) * ABUFH + (r + 64 * i) * GLDH + kq * 4] = ra[i]; \
        _Pragma("unroll")                                                       \
        for (int i = 0; i < 4; i++)                                             \
            *(uint2*)&Bs[(buf) * BBUFH + (r + 64 * i) * GLDH + kq * 4] = f4_to_h4(rb[i]); \
    }

    P_LOAD(0); P_STS(0); __syncthreads();

    const int NIT = CDIM / GBK;
    for (int it = 0; it < NIT; ++it) {
        const int buf = it & 1;
        if (it + 1 < NIT) P_LOAD(it + 1);

        const uint32_t aB = asBase + (uint32_t)buf * (ABUFH * 2);
        const uint32_t bB = bsBase + (uint32_t)buf * (BBUFH * 2);

#pragma unroll
        for (int kk = 0; kk < 2; kk++) {
            uint32_t a[2][4], bf[8][2];
#pragma unroll
            for (int mi = 0; mi < 2; mi++) {
                uint32_t addr = aB + aOff + (uint32_t)(mi * 16 * GLDH * 2) + (uint32_t)(kk * 32);
                LDSM_X4(a[mi][0], a[mi][1], a[mi][2], a[mi][3], addr);
            }
#pragma unroll
            for (int p = 0; p < 4; p++) {
                uint32_t addr = bB + bOff + (uint32_t)(p * 16 * GLDH * 2) + (uint32_t)(kk * 32);
                uint32_t r0, r1, r2, r3;
                LDSM_X4(r0, r1, r2, r3, addr);
                bf[2 * p][0] = r0; bf[2 * p][1] = r1;
                bf[2 * p + 1][0] = r2; bf[2 * p + 1][1] = r3;
            }
#pragma unroll
            for (int mi = 0; mi < 2; mi++)
#pragma unroll
                for (int ni = 0; ni < 8; ni++)
                    MMA_F16(acc[mi][ni], a[mi][0], a[mi][1], a[mi][2], a[mi][3],
                            bf[ni][0], bf[ni][1]);
        }
        if (it + 1 < NIT) P_STS(buf ^ 1);
        __syncthreads();
    }

    const int g  = lane >> 2;
    const int cq = (lane & 3) * 2;
#pragma unroll
    for (int mi = 0; mi < 2; mi++) {
        const int row0 = rowBase + warpM + mi * 16 + g;
#pragma unroll
        for (int ni = 0; ni < 8; ni++) {
            const int col = colBase + warpN + ni * 8 + cq;
            float b0 = bias[col], b1 = bias[col + 1];
            *(float2*)&C[(size_t)row0 * CDIM + col] =
                make_float2(acc[mi][ni][0] + b0, acc[mi][ni][1] + b1);
            *(float2*)&C[(size_t)(row0 + 8) * CDIM + col] =
                make_float2(acc[mi][ni][2] + b0, acc[mi][ni][3] + b1);
        }
    }
#undef P_LOAD
#undef P_STS
}

// =========================================================================
// CPB MLP table + bias gather (tiny, unchanged)
// =========================================================================
__global__ __launch_bounds__(512)
void cpb_tbl_kernel(const float* __restrict__ rel_table,
                    const float* __restrict__ w1,
                    const float* __restrict__ b1,
                    const float* __restrict__ w2,
                    float* __restrict__ tbl)
{
    __shared__ float hid[CPBH];
    int p = blockIdx.x;
    float t0 = rel_table[2 * p], t1 = rel_table[2 * p + 1];
    int j = threadIdx.x;
    hid[j] = fmaxf(t0 * w1[2 * j] + t1 * w1[2 * j + 1] + b1[j], 0.f);
    __syncthreads();

    int warp = j >> 5, lane = j & 31;
    const float* w2h = w2 + warp * CPBH;
    float s = 0.f;
#pragma unroll
    for (int q = lane; q < CPBH; q += 32) s += hid[q] * w2h[q];
#pragma unroll
    for (int o = 16; o > 0; o >>= 1) s += __shfl_xor_sync(0xffffffffu, s, o);
    if (lane == 0) tbl[p * HEADS + warp] = s;
}

__global__ void bias_gather_kernel(const float* __restrict__ tbl,
                                   const int* __restrict__ rel_index,
                                   float* __restrict__ bias)
{
    int t = blockIdx.x * blockDim.x + threadIdx.x;
    const int TOT = HEADS * NTOK * NTOK;
    if (t >= TOT) return;
    int h  = t / (NTOK * NTOK);
    int ij = t % (NTOK * NTOK);
    float x = tbl[rel_index[ij] * HEADS + h];
    bias[(size_t)h * NTOK * NTOK + ij] = 16.f / (1.f + __expf(-x));
}

// =========================================================================
// Window attention v9: interleaved q/k inputs, fp16 output.
// =========================================================================
#define KSTR_H 40
#define VSTR_H 152
#define PVSTR  18

#define AK_KHI 0
#define AK_KLO (AK_KHI + NTOK * KSTR_H * 2)
#define AK_VHI (AK_KLO + NTOK * KSTR_H * 2)
#define AK_PVB (AK_VHI + DHEAD * VSTR_H * 2)
#define AK_SUM (AK_PVB + 9 * 32 * PVSTR * 4)
#define ATTN_SMEM_BYTES (AK_SUM + 9 * 2 * 32 * 4)

__global__ __launch_bounds__(576, 1)
void attn_tc9_kernel(const uint2* __restrict__ qs,
                     const uint2* __restrict__ ks,
                     const __half* __restrict__ vh,
                     const float* __restrict__ bias,
                     const float* __restrict__ mask,
                     __half* __restrict__ outH)
{
    extern __shared__ __align__(16) char dsm[];

    const int h = blockIdx.x;
    const int b = blockIdx.y;
    const int w = b & (NW - 1);

    const int tid  = threadIdx.x;
    const int lane = tid & 31;
    const int warp = tid >> 5;
    const int pair = warp % 9;
    const int half = warp / 9;
    const int ng   = half ? 5 : 4;
    const int hbase = half ? 64 : 0;
    const int g  = lane >> 2;
    const int t  = lane & 3;
    const int R0 = pair * 16;

    const size_t rowB = (size_t)b * NTOK;
    const size_t hOff = (size_t)h * DHEAD;
    const size_t pOff = hOff >> 1;                 // column-pair offset

    __half* knHi = (__half*)(dsm + AK_KHI);
    __half* knLo = (__half*)(dsm + AK_KLO);
    __half* vtHi = (__half*)(dsm + AK_VHI);
    float*  pvb  = (float*)(dsm + AK_PVB);
    float*  sumb = (float*)(dsm + AK_SUM);
    const uint32_t knHiB = s2u(knHi);
    const uint32_t knLoB = s2u(knLo);
    const uint32_t vtHiB = s2u(vtHi);

    // ---------- PHASE 0: front-batched loads ----------
    // K hi/lo: 4 x LDG.64 (lane -> (row parity, column pair))
    const int p16 = lane & 15, h16 = lane >> 4;
    uint2 khl[4];
#pragma unroll
    for (int i = 0; i < 4; i++) {
        int j = warp * 8 + 2 * i + h16;
        khl[i] = ks[(rowB + j) * (CDIM / 2) + pOff + p16];
    }
    // V: 8 x LDG.16
    __half vhr[8];
#pragma unroll
    for (int i = 0; i < 8; i++) {
        int j = warp * 8 + i;
        vhr[i] = vh[(rowB + j) * CDIM + hOff + lane];
    }
    // Q fragments: 8 x LDG.64 (hi in .x, lo in .y)
    uint32_t qah[2][4], qal[2][4];
    {
        const uint2* q0 = qs + (rowB + R0 + g) * (CDIM / 2) + pOff;
        const uint2* q1 = q0 + 8 * (CDIM / 2);
#pragma unroll
        for (int kc = 0; kc < 2; kc++) {
            uint2 u;
            u = q0[8 * kc + t];     qah[kc][0] = u.x; qal[kc][0] = u.y;
            u = q1[8 * kc + t];     qah[kc][1] = u.x; qal[kc][1] = u.y;
            u = q0[8 * kc + 4 + t]; qah[kc][2] = u.x; qal[kc][2] = u.y;
            u = q1[8 * kc + 4 + t]; qah[kc][3] = u.x; qal[kc][3] = u.y;
        }
    }
    // bias + mask -> acc
    float acc[10][4];
    {
        const float* biasR0 = bias + (size_t)h * NTOK * NTOK + (size_t)(R0 + g) * NTOK + hbase + 2 * t;
        const float* biasR1 = biasR0 + 8 * NTOK;
        const float* maskR0 = mask + (size_t)w * NTOK * NTOK + (size_t)(R0 + g) * NTOK + hbase + 2 * t;
        const float* maskR1 = maskR0 + 8 * NTOK;
#pragma unroll
        for (int nt = 0; nt < 10; nt++) {
            if (nt < 2 * ng) {
                float2 bb0 = *(const float2*)(biasR0 + 8 * nt);
                float2 mm0 = *(const float2*)(maskR0 + 8 * nt);
                float2 bb1 = *(const float2*)(biasR1 + 8 * nt);
                float2 mm1 = *(const float2*)(maskR1 + 8 * nt);
                acc[nt][0] = bb0.x + mm0.x;
                acc[nt][1] = bb0.y + mm0.y;
                acc[nt][2] = bb1.x + mm1.x;
                acc[nt][3] = bb1.y + mm1.y;
            } else {
#pragma unroll
                for (int c = 0; c < 4; c++) acc[nt][c] = 0.f;
            }
        }
    }

    // ---------- PHASE 1: stores to smem ----------
#pragma unroll
    for (int i = 0; i < 4; i++) {
        int j = warp * 8 + 2 * i + h16;
        *(uint32_t*)&knHi[j * KSTR_H + 2 * p16] = khl[i].x;
        *(uint32_t*)&knLo[j * KSTR_H + 2 * p16] = khl[i].y;
    }
#pragma unroll
    for (int i = 0; i < 8; i++) {
        int j = warp * 8 + i;
        vtHi[lane * VSTR_H + j] = vhr[i];
    }
    __syncthreads();

    // ---------- QK^T (split fp16, 3 terms) onto bias+mask ----------
    const uint32_t ldsmRow = (uint32_t)((lane & 7) + ((lane & 16) ? 8 : 0));
    const uint32_t ldsmCol = (uint32_t)((lane >> 3) & 1) * 16;

#pragma unroll
    for (int kc = 0; kc < 2; kc++) {
#pragma unroll
        for (int gI = 0; gI < 5; gI++) {
            if (gI < ng) {
                uint32_t off = (uint32_t)(hbase + gI * 16 + ldsmRow) * (KSTR_H * 2)
                             + ldsmCol + (uint32_t)kc * 32;
                uint32_t bh0, bh1, bh2, bh3, bl0, bl1, bl2, bl3;
                LDSM_X4(bh0, bh1, bh2, bh3, knHiB + off);
                LDSM_X4(bl0, bl1, bl2, bl3, knLoB + off);
                MMA_F16(acc[2 * gI],     qah[kc][0], qah[kc][1], qah[kc][2], qah[kc][3], bh0, bh1);
                MMA_F16(acc[2 * gI],     qah[kc][0], qah[kc][1], qah[kc][2], qah[kc][3], bl0, bl1);
                MMA_F16(acc[2 * gI],     qal[kc][0], qal[kc][1], qal[kc][2], qal[kc][3], bh0, bh1);
                MMA_F16(acc[2 * gI + 1], qah[kc][0], qah[kc][1], qah[kc][2], qah[kc][3], bh2, bh3);
                MMA_F16(acc[2 * gI + 1], qah[kc][0], qah[kc][1], qah[kc][2], qah[kc][3], bl2, bl3);
                MMA_F16(acc[2 * gI + 1], qal[kc][0], qal[kc][1], qal[kc][2], qal[kc][3], bh2, bh3);
            }
        }
    }

    // ---------- local max, exp, local sums ----------
    float mx0 = -1e30f, mx1 = -1e30f, sm0 = 0.f, sm1 = 0.f;
    {
#pragma unroll
        for (int nt = 0; nt < 10; nt++) {
            if (nt < 2 * ng) {
                mx0 = fmaxf(mx0, fmaxf(acc[nt][0], acc[nt][1]));
                mx1 = fmaxf(mx1, fmaxf(acc[nt][2], acc[nt][3]));
            }
        }
        mx0 = fmaxf(mx0, __shfl_xor_sync(0xffffffffu, mx0, 1));
        mx0 = fmaxf(mx0, __shfl_xor_sync(0xffffffffu, mx0, 2));
        mx1 = fmaxf(mx1, __shfl_xor_sync(0xffffffffu, mx1, 1));
        mx1 = fmaxf(mx1, __shfl_xor_sync(0xffffffffu, mx1, 2));
#pragma unroll
        for (int nt = 0; nt < 10; nt++) {
            if (nt < 2 * ng) {
                acc[nt][0] = __expf(acc[nt][0] - mx0);
                acc[nt][1] = __expf(acc[nt][1] - mx0);
                acc[nt][2] = __expf(acc[nt][2] - mx1);
                acc[nt][3] = __expf(acc[nt][3] - mx1);
                sm0 += acc[nt][0] + acc[nt][1];
                sm1 += acc[nt][2] + acc[nt][3];
            }
        }
        sm0 += __shfl_xor_sync(0xffffffffu, sm0, 1);
        sm0 += __shfl_xor_sync(0xffffffffu, sm0, 2);
        sm1 += __shfl_xor_sync(0xffffffffu, sm1, 1);
        sm1 += __shfl_xor_sync(0xffffffffu, sm1, 2);
        if (t == 0) {
            float* sb = sumb + (pair * 2 + half) * 32;
            sb[g]          = sm0;
            sb[g + 8]      = sm1;
            sb[16 + g]     = mx0;
            sb[16 + g + 8] = mx1;
        }
    }

    // ---------- PV (plain fp16) ----------
    float pv[4][4];
#pragma unroll
    for (int nt = 0; nt < 4; nt++)
#pragma unroll
        for (int c = 0; c < 4; c++) pv[nt][c] = 0.f;

#pragma unroll
    for (int kc2 = 0; kc2 < 5; kc2++) {
        if (kc2 < ng) {
            uint32_t ph[4];
            ph[0] = pack_h2(acc[2 * kc2][0],     acc[2 * kc2][1]);
            ph[1] = pack_h2(acc[2 * kc2][2],     acc[2 * kc2][3]);
            ph[2] = pack_h2(acc[2 * kc2 + 1][0], acc[2 * kc2 + 1][1]);
            ph[3] = pack_h2(acc[2 * kc2 + 1][2], acc[2 * kc2 + 1][3]);
            const uint32_t gk = (uint32_t)((hbase >> 4) + kc2);
#pragma unroll
            for (int p = 0; p < 2; p++) {
                uint32_t off = (uint32_t)(p * 16 + ldsmRow) * (VSTR_H * 2)
                             + ldsmCol + gk * 32;
                uint32_t bh0, bh1, bh2, bh3;
                LDSM_X4(bh0, bh1, bh2, bh3, vtHiB + off);
                MMA_F16(pv[2 * p],     ph[0], ph[1], ph[2], ph[3], bh0, bh1);
                MMA_F16(pv[2 * p + 1], ph[0], ph[1], ph[2], ph[3], bh2, bh3);
            }
        }
    }

    // ---------- pairwise combine + fp16 epilogue ----------
    if (half == 1) {
        float* pb = pvb + (pair * 32 + lane) * PVSTR;
#pragma unroll
        for (int nt = 0; nt < 4; nt++) {
            *(float2*)(pb + nt * 4)     = make_float2(pv[nt][0], pv[nt][1]);
            *(float2*)(pb + nt * 4 + 2) = make_float2(pv[nt][2], pv[nt][3]);
        }
    }
    __syncthreads();
    if (half == 0) {
        const float* sbO = sumb + (pair * 2 + 1) * 32;
        const float smO0 = sbO[g],      mxO0 = sbO[16 + g];
        const float smO1 = sbO[g + 8],  mxO1 = sbO[16 + g + 8];
        const float M0 = fmaxf(mx0, mxO0);
        const float M1 = fmaxf(mx1, mxO1);
        const float fl0 = __expf(mx0 - M0), fo0 = __expf(mxO0 - M0);
        const float fl1 = __expf(mx1 - M1), fo1 = __expf(mxO1 - M1);
        const float inv0 = 1.f / (sm0 * fl0 + smO0 * fo0);
        const float inv1 = 1.f / (sm1 * fl1 + smO1 * fo1);
        const float* pb = pvb + (pair * 32 + lane) * PVSTR;
        __half* o0 = outH + (rowB + R0 + g) * CDIM + hOff + 2 * t;
        __half* o1 = o0 + (size_t)8 * CDIM;
#pragma unroll
        for (int nt = 0; nt < 4; nt++) {
            float2 q0 = *(const float2*)(pb + nt * 4);
            float2 q1 = *(const float2*)(pb + nt * 4 + 2);
            *(uint32_t*)(o0 + 8 * nt) = pack_h2((pv[nt][0] * fl0 + q0.x * fo0) * inv0,
                                                (pv[nt][1] * fl0 + q0.y * fo0) * inv0);
            *(uint32_t*)(o1 + 8 * nt) = pack_h2((pv[nt][2] * fl1 + q1.x * fo1) * inv1,
                                                (pv[nt][3] * fl1 + q1.y * fo1) * inv1);
        }
    }
}

// =========================================================================
// launch
// =========================================================================
extern "C" void kernel_launch(void* const* d_in, const int* in_sizes, int n_in,
                              void* d_out, int out_size)
{
    const float* x           = (const float*)d_in[0];
    const float* mask        = (const float*)d_in[1];
    const float* qkv_w       = (const float*)d_in[2];
    const float* logit_scale = (const float*)d_in[3];
    const float* cpb_w1      = (const float*)d_in[4];
    const float* cpb_b1      = (const float*)d_in[5];
    const float* cpb_w2      = (const float*)d_in[6];
    const float* proj_w      = (const float*)d_in[7];
    const float* proj_b      = (const float*)d_in[8];
    const float* rel_table   = (const float*)d_in[9];
    const int*   rel_index   = (const int*)d_in[10];
    float* out = (float*)d_out;

    uint2 *qsP, *ksP;
    __half *vhP, *attH;
    float *tbl, *bias;
    cudaGetSymbolAddress((void**)&qsP,  g_qs);
    cudaGetSymbolAddress((void**)&ksP,  g_ks);
    cudaGetSymbolAddress((void**)&vhP,  g_vh);
    cudaGetSymbolAddress((void**)&attH, g_attH);
    cudaGetSymbolAddress((void**)&tbl,  g_tbl);
    cudaGetSymbolAddress((void**)&bias, g_bias);

    cudaFuncSetAttribute(gemm_qkv_fused,
                         cudaFuncAttributeMaxDynamicSharedMemorySize, GT_SMEM_BYTES);
    cudaFuncSetAttribute(gemm_proj,
                         cudaFuncAttributeMaxDynamicSharedMemorySize, GT_SMEM_BYTES);
    cudaFuncSetAttribute(attn_tc9_kernel,
                         cudaFuncAttributeMaxDynamicSharedMemorySize, ATTN_SMEM_BYTES);

    // 1) QKV projection + fused normalize/split epilogue (coalesced stores)
    {
        dim3 grid(QKVC / 256, MROWS / 128);
        gemm_qkv_fused<<<grid, 512, GT_SMEM_BYTES>>>(x, qkv_w, logit_scale,
                                                     qsP, ksP, vhP);
    }

    // 2) relative position bias table + gather
    cpb_tbl_kernel<<<NPOS, CPBH>>>(rel_table, cpb_w1, cpb_b1, cpb_w2, tbl);
    {
        int tot = HEADS * NTOK * NTOK;
        bias_gather_kernel<<<(tot + 255) / 256, 256>>>(tbl, rel_index, bias);
    }

    // 3) attention v9 (interleaved q/k inputs, fp16 output)
    {
        dim3 grid(HEADS, BWIN);
        attn_tc9_kernel<<<grid, 576, ATTN_SMEM_BYTES>>>(qsP, ksP, vhP,
                                                        bias, mask, attH);
    }

    // 4) output projection (fp16 A path)
    {
        dim3 grid(CDIM / 256, MROWS / 128);
        gemm_proj<<<grid, 512, GT_SMEM_BYTES>>>(attH, proj_w, proj_b, out);
    }
}

// round 16
// speedup vs baseline: 1.1328x; 1.0095x over previous
#include <cuda_runtime.h>
#include <cuda_bf16.h>
#include <cuda_fp16.h>
#include <math.h>
#include <stdint.h>

// ---------------- problem constants ----------------
#define BWIN   512
#define NTOK   144
#define CDIM   512
#define HEADS  16
#define DHEAD  32
#define NW     64
#define MROWS  (BWIN * NTOK)        // 73728
#define QKVC   (3 * CDIM)           // 1536
#define NPOS   (23 * 23)
#define CPBH   512

// ---------------- scratch ----------------
__device__ uint2  g_qs[(size_t)MROWS * (CDIM / 2)];
__device__ uint2  g_ks[(size_t)MROWS * (CDIM / 2)];
__device__ __half g_vh[(size_t)MROWS * CDIM];
__device__ __half g_attH[(size_t)MROWS * CDIM];
__device__ float  g_tbl [NPOS * HEADS];
__device__ float  g_bias[(size_t)HEADS * NTOK * NTOK];

__device__ __forceinline__ uint32_t s2u(const void* p) {
    return (uint32_t)__cvta_generic_to_shared(p);
}
__device__ __forceinline__ uint2 f4_to_h4(float4 v) {
    __half2 h0 = __float22half2_rn(make_float2(v.x, v.y));
    __half2 h1 = __float22half2_rn(make_float2(v.z, v.w));
    uint2 u;
    u.x = *(uint32_t*)&h0;
    u.y = *(uint32_t*)&h1;
    return u;
}
__device__ __forceinline__ void split_pack(float x, float y, uint32_t& hi, uint32_t& lo) {
    __half hx = __float2half_rn(x), hy = __float2half_rn(y);
    __half2 h = __halves2half2(hx, hy);
    hi = *(uint32_t*)&h;
    __half2 l = __floats2half2_rn(x - __half2float(hx), y - __half2float(hy));
    lo = *(uint32_t*)&l;
}
__device__ __forceinline__ uint32_t pack_h2(float x, float y) {
    __half2 h = __floats2half2_rn(x, y);
    return *(uint32_t*)&h;
}

#define MMA_F16(d, a0,a1,a2,a3, b0,b1)                                         \
    asm volatile("mma.sync.aligned.m16n8k16.row.col.f32.f16.f16.f32 "          \
                 "{%0,%1,%2,%3},{%4,%5,%6,%7},{%8,%9},{%0,%1,%2,%3};"          \
                 : "+f"(d[0]), "+f"(d[1]), "+f"(d[2]), "+f"(d[3])              \
                 : "r"(a0), "r"(a1), "r"(a2), "r"(a3), "r"(b0), "r"(b1))

// fp16-accumulate variant (full-rate hypothesis); d0={r0c0,r0c1}, d1={r1c0,r1c1}
#define MMA_F16ACC(d0, d1, a0,a1,a2,a3, b0,b1)                                 \
    asm volatile("mma.sync.aligned.m16n8k16.row.col.f16.f16.f16.f16 "          \
                 "{%0,%1},{%2,%3,%4,%5},{%6,%7},{%0,%1};"                      \
                 : "+r"(d0), "+r"(d1)                                          \
                 : "r"(a0), "r"(a1), "r"(a2), "r"(a3), "r"(b0), "r"(b1))

#define LDSM_X4(r0,r1,r2,r3, addr)                                             \
    asm volatile("ldmatrix.sync.aligned.m8n8.x4.shared.b16 {%0,%1,%2,%3}, [%4];" \
                 : "=r"(r0), "=r"(r1), "=r"(r2), "=r"(r3) : "r"(addr))

// =========================================================================
// Shared GEMM config (proven mainloop, fp32 A + fp32 B)
// =========================================================================
#define GBK    32
#define GLDH   40
#define ABUFH  (128 * GLDH)
#define BBUFH  (256 * GLDH)
#define GT_SMEM_BYTES ((2 * ABUFH + 2 * BBUFH) * 2)   // 61440

#define GEMM_MAINLOOP_BODY(A_, B_, K_)                                          \
    extern __shared__ __align__(16) __half gsm[];                               \
    __half* As = gsm;                                                           \
    __half* Bs = gsm + 2 * ABUFH;                                               \
    const int tid  = threadIdx.x;                                               \
    const int lane = tid & 31;                                                  \
    const int warp = tid >> 5;                                                  \
    const int warpM = (warp & 3) * 32;                                          \
    const int warpN = (warp >> 2) * 64;                                         \
    const int rowBase = blockIdx.y * 128;                                       \
    const int colBase = blockIdx.x * 256;                                       \
    const int r  = tid >> 3;                                                    \
    const int kq = tid & 7;                                                     \
    const float* Ag = (A_) + (size_t)(rowBase + r) * (K_) + kq * 4;             \
    const float* Bg = (B_) + (size_t)(colBase + r) * (K_) + kq * 4;             \
    float4 ra[2], rb[4];                                                        \
    float acc[2][8][4];                                                         \
    _Pragma("unroll")                                                           \
    for (int mi = 0; mi < 2; mi++)                                              \
        _Pragma("unroll")                                                       \
        for (int ni = 0; ni < 8; ni++)                                          \
            _Pragma("unroll")                                                   \
            for (int c = 0; c < 4; c++) acc[mi][ni][c] = 0.f;                   \
    const uint32_t aOff = (uint32_t)((warpM + (lane & 7) + ((lane >> 3) & 1) * 8) * (GLDH * 2)) \
                        + (uint32_t)(lane >> 4) * 16;                           \
    const uint32_t bOff = (uint32_t)((warpN + (lane & 7) + ((lane & 16) ? 8 : 0)) * (GLDH * 2)) \
                        + (uint32_t)((lane >> 3) & 1) * 16;                     \
    const uint32_t asBase = s2u(As);                                            \
    const uint32_t bsBase = s2u(Bs);                                            \
    {                                                                           \
        const float* ap = Ag; const float* bp = Bg;                             \
        ra[0] = *(const float4*)(ap);                                           \
        ra[1] = *(const float4*)(ap + (size_t)64 * (K_));                       \
        rb[0] = *(const float4*)(bp);                                           \
        rb[1] = *(const float4*)(bp + (size_t)64 * (K_));                       \
        rb[2] = *(const float4*)(bp + (size_t)128 * (K_));                      \
        rb[3] = *(const float4*)(bp + (size_t)192 * (K_));                      \
        _Pragma("unroll")                                                       \
        for (int i = 0; i < 2; i++)                                             \
            *(uint2*)&As[(r + 64 * i) * GLDH + kq * 4] = f4_to_h4(ra[i]);       \
        _Pragma("unroll")                                                       \
        for (int i = 0; i < 4; i++)                                             \
            *(uint2*)&Bs[(r + 64 * i) * GLDH + kq * 4] = f4_to_h4(rb[i]);       \
    }                                                                           \
    __syncthreads();                                                            \
    const int NIT = (K_) / GBK;                                                 \
    for (int it = 0; it < NIT; ++it) {                                          \
        const int buf = it & 1;                                                 \
        if (it + 1 < NIT) {                                                     \
            const float* ap = Ag + (it + 1) * GBK;                              \
            const float* bp = Bg + (it + 1) * GBK;                              \
            ra[0] = *(const float4*)(ap);                                       \
            ra[1] = *(const float4*)(ap + (size_t)64 * (K_));                   \
            rb[0] = *(const float4*)(bp);                                       \
            rb[1] = *(const float4*)(bp + (size_t)64 * (K_));                   \
            rb[2] = *(const float4*)(bp + (size_t)128 * (K_));                  \
            rb[3] = *(const float4*)(bp + (size_t)192 * (K_));                  \
        }                                                                       \
        const uint32_t aB = asBase + (uint32_t)buf * (ABUFH * 2);               \
        const uint32_t bB = bsBase + (uint32_t)buf * (BBUFH * 2);               \
        _Pragma("unroll")                                                       \
        for (int kk = 0; kk < 2; kk++) {                                        \
            uint32_t a[2][4], bf[8][2];                                         \
            _Pragma("unroll")                                                   \
            for (int mi = 0; mi < 2; mi++) {                                    \
                uint32_t addr = aB + aOff + (uint32_t)(mi * 16 * GLDH * 2) + (uint32_t)(kk * 32); \
                LDSM_X4(a[mi][0], a[mi][1], a[mi][2], a[mi][3], addr);          \
            }                                                                   \
            _Pragma("unroll")                                                   \
            for (int p = 0; p < 4; p++) {                                       \
                uint32_t addr = bB + bOff + (uint32_t)(p * 16 * GLDH * 2) + (uint32_t)(kk * 32); \
                uint32_t r0, r1, r2, r3;                                        \
                LDSM_X4(r0, r1, r2, r3, addr);                                  \
                bf[2 * p][0] = r0; bf[2 * p][1] = r1;                           \
                bf[2 * p + 1][0] = r2; bf[2 * p + 1][1] = r3;                   \
            }                                                                   \
            _Pragma("unroll")                                                   \
            for (int mi = 0; mi < 2; mi++)                                      \
                _Pragma("unroll")                                               \
                for (int ni = 0; ni < 8; ni++)                                  \
                    MMA_F16(acc[mi][ni], a[mi][0], a[mi][1], a[mi][2], a[mi][3],\
                            bf[ni][0], bf[ni][1]);                              \
        }                                                                       \
        if (it + 1 < NIT) {                                                     \
            const int nb = buf ^ 1;                                             \
            _Pragma("unroll")                                                   \
            for (int i = 0; i < 2; i++)                                         \
                *(uint2*)&As[nb * ABUFH + (r + 64 * i) * GLDH + kq * 4] = f4_to_h4(ra[i]); \
            _Pragma("unroll")                                                   \
            for (int i = 0; i < 4; i++)                                         \
                *(uint2*)&Bs[nb * BBUFH + (r + 64 * i) * GLDH + kq * 4] = f4_to_h4(rb[i]); \
        }                                                                       \
        __syncthreads();                                                        \
    }

// =========================================================================
// QKV GEMM with fused normalize+split epilogue (interleaved hi/lo stores)
// =========================================================================
__global__ __launch_bounds__(512, 1)
void gemm_qkv_fused(const float* __restrict__ A,
                    const float* __restrict__ B,
                    const float* __restrict__ logit_scale,
                    uint2* __restrict__ qs, uint2* __restrict__ ks,
                    __half* __restrict__ vh)
{
    GEMM_MAINLOOP_BODY(A, B, CDIM)

    const int g  = lane >> 2;
    const int region = (colBase + warpN) >> 9;
    const int colLoc = (colBase + warpN) & 511;
    const int cq = (lane & 3) * 2;

    if (region == 2) {
#pragma unroll
        for (int mi = 0; mi < 2; mi++) {
            const size_t r0 = (size_t)(rowBase + warpM + mi * 16 + g);
#pragma unroll
            for (int ni = 0; ni < 8; ni++) {
                const int cl = colLoc + ni * 8 + cq;
                *(uint32_t*)&vh[r0 * CDIM + cl] =
                    pack_h2(acc[mi][ni][0], acc[mi][ni][1]);
                *(uint32_t*)&vh[(r0 + 8) * CDIM + cl] =
                    pack_h2(acc[mi][ni][2], acc[mi][ni][3]);
            }
        }
        return;
    }

    uint2* dst = (region == 0) ? qs : ks;
    float gscale[2] = {1.f, 1.f};
    if (region == 0) {
#pragma unroll
        for (int grp = 0; grp < 2; grp++) {
            int head = (colLoc >> 5) + grp;
            gscale[grp] = __expf(fminf(logit_scale[head], 4.60517018598809f));
        }
    }

#pragma unroll
    for (int mi = 0; mi < 2; mi++) {
        const size_t r0 = (size_t)(rowBase + warpM + mi * 16 + g);
#pragma unroll
        for (int grp = 0; grp < 2; grp++) {
            float s0 = 0.f, s1 = 0.f;
#pragma unroll
            for (int ni = 4 * grp; ni < 4 * grp + 4; ni++) {
                s0 += acc[mi][ni][0] * acc[mi][ni][0] + acc[mi][ni][1] * acc[mi][ni][1];
                s1 += acc[mi][ni][2] * acc[mi][ni][2] + acc[mi][ni][3] * acc[mi][ni][3];
            }
            s0 += __shfl_xor_sync(0xffffffffu, s0, 1);
            s0 += __shfl_xor_sync(0xffffffffu, s0, 2);
            s1 += __shfl_xor_sync(0xffffffffu, s1, 1);
            s1 += __shfl_xor_sync(0xffffffffu, s1, 2);
            float rn0 = rsqrtf(s0) * gscale[grp];
            float rn1 = rsqrtf(s1) * gscale[grp];
#pragma unroll
            for (int ni = 4 * grp; ni < 4 * grp + 4; ni++) {
                const int pr = (colLoc + ni * 8 + cq) >> 1;
                uint32_t hi, lo;
                split_pack(acc[mi][ni][0] * rn0, acc[mi][ni][1] * rn0, hi, lo);
                dst[r0 * (CDIM / 2) + pr] = make_uint2(hi, lo);
                split_pack(acc[mi][ni][2] * rn1, acc[mi][ni][3] * rn1, hi, lo);
                dst[(r0 + 8) * (CDIM / 2) + pr] = make_uint2(hi, lo);
            }
        }
    }
}

// =========================================================================
// Output projection: A = fp16 attention output, B fp32
// =========================================================================
__global__ __launch_bounds__(512, 1)
void gemm_proj(const __half* __restrict__ A,
               const float* __restrict__ B,
               const float* __restrict__ bias,
               float* __restrict__ C)
{
    extern __shared__ __align__(16) __half gsm[];
    __half* As = gsm;
    __half* Bs = gsm + 2 * ABUFH;

    const int tid  = threadIdx.x;
    const int lane = tid & 31;
    const int warp = tid >> 5;
    const int warpM = (warp & 3) * 32;
    const int warpN = (warp >> 2) * 64;
    const int rowBase = blockIdx.y * 128;
    const int colBase = blockIdx.x * 256;

    const int r  = tid >> 3;
    const int kq = tid & 7;
    const __half* Ag = A + (size_t)(rowBase + r) * CDIM + kq * 4;
    const float*  Bg = B + (size_t)(colBase + r) * CDIM + kq * 4;

    uint2 ra[2];
    float4 rb[4];

    float acc[2][8][4];
#pragma unroll
    for (int mi = 0; mi < 2; mi++)
#pragma unroll
        for (int ni = 0; ni < 8; ni++)
#pragma unroll
            for (int c = 0; c < 4; c++) acc[mi][ni][c] = 0.f;

    const uint32_t aOff = (uint32_t)((warpM + (lane & 7) + ((lane >> 3) & 1) * 8) * (GLDH * 2))
                        + (uint32_t)(lane >> 4) * 16;
    const uint32_t bOff = (uint32_t)((warpN + (lane & 7) + ((lane & 16) ? 8 : 0)) * (GLDH * 2))
                        + (uint32_t)((lane >> 3) & 1) * 16;
    const uint32_t asBase = s2u(As);
    const uint32_t bsBase = s2u(Bs);

#define P_LOAD(it)  {                                                \
        const __half* ap = Ag + (it) * GBK;                          \
        const float*  bp = Bg + (it) * GBK;                          \
        ra[0] = *(const uint2*)(ap);                                 \
        ra[1] = *(const uint2*)(ap + (size_t)64 * CDIM);             \
        rb[0] = *(const float4*)(bp);                                \
        rb[1] = *(const float4*)(bp + (size_t)64 * CDIM);            \
        rb[2] = *(const float4*)(bp + (size_t)128 * CDIM);           \
        rb[3] = *(const float4*)(bp + (size_t)192 * CDIM);           \
    }
#define P_STS(buf)  {                                                           \
        _Pragma("unroll")                                                       \
        for (int i = 0; i < 2; i++)                                             \
            *(uint2*)&As[(buf) * ABUFH + (r + 64 * i) * GLDH + kq * 4] = ra[i]; \
        _Pragma("unroll")                                                       \
        for (int i = 0; i < 4; i++)                                             \
            *(uint2*)&Bs[(buf) * BBUFH + (r + 64 * i) * GLDH + kq * 4] = f4_to_h4(rb[i]); \
    }

    P_LOAD(0); P_STS(0); __syncthreads();

    const int NIT = CDIM / GBK;
    for (int it = 0; it < NIT; ++it) {
        const int buf = it & 1;
        if (it + 1 < NIT) P_LOAD(it + 1);

        const uint32_t aB = asBase + (uint32_t)buf * (ABUFH * 2);
        const uint32_t bB = bsBase + (uint32_t)buf * (BBUFH * 2);

#pragma unroll
        for (int kk = 0; kk < 2; kk++) {
            uint32_t a[2][4], bf[8][2];
#pragma unroll
            for (int mi = 0; mi < 2; mi++) {
                uint32_t addr = aB + aOff + (uint32_t)(mi * 16 * GLDH * 2) + (uint32_t)(kk * 32);
                LDSM_X4(a[mi][0], a[mi][1], a[mi][2], a[mi][3], addr);
            }
#pragma unroll
            for (int p = 0; p < 4; p++) {
                uint32_t addr = bB + bOff + (uint32_t)(p * 16 * GLDH * 2) + (uint32_t)(kk * 32);
                uint32_t r0, r1, r2, r3;
                LDSM_X4(r0, r1, r2, r3, addr);
                bf[2 * p][0] = r0; bf[2 * p][1] = r1;
                bf[2 * p + 1][0] = r2; bf[2 * p + 1][1] = r3;
            }
#pragma unroll
            for (int mi = 0; mi < 2; mi++)
#pragma unroll
                for (int ni = 0; ni < 8; ni++)
                    MMA_F16(acc[mi][ni], a[mi][0], a[mi][1], a[mi][2], a[mi][3],
                            bf[ni][0], bf[ni][1]);
        }
        if (it + 1 < NIT) P_STS(buf ^ 1);
        __syncthreads();
    }

    const int g  = lane >> 2;
    const int cq = (lane & 3) * 2;
#pragma unroll
    for (int mi = 0; mi < 2; mi++) {
        const int row0 = rowBase + warpM + mi * 16 + g;
#pragma unroll
        for (int ni = 0; ni < 8; ni++) {
            const int col = colBase + warpN + ni * 8 + cq;
            float b0 = bias[col], b1 = bias[col + 1];
            *(float2*)&C[(size_t)row0 * CDIM + col] =
                make_float2(acc[mi][ni][0] + b0, acc[mi][ni][1] + b1);
            *(float2*)&C[(size_t)(row0 + 8) * CDIM + col] =
                make_float2(acc[mi][ni][2] + b0, acc[mi][ni][3] + b1);
        }
    }
#undef P_LOAD
#undef P_STS
}

// =========================================================================
// CPB MLP table + bias gather (tiny, unchanged)
// =========================================================================
__global__ __launch_bounds__(512)
void cpb_tbl_kernel(const float* __restrict__ rel_table,
                    const float* __restrict__ w1,
                    const float* __restrict__ b1,
                    const float* __restrict__ w2,
                    float* __restrict__ tbl)
{
    __shared__ float hid[CPBH];
    int p = blockIdx.x;
    float t0 = rel_table[2 * p], t1 = rel_table[2 * p + 1];
    int j = threadIdx.x;
    hid[j] = fmaxf(t0 * w1[2 * j] + t1 * w1[2 * j + 1] + b1[j], 0.f);
    __syncthreads();

    int warp = j >> 5, lane = j & 31;
    const float* w2h = w2 + warp * CPBH;
    float s = 0.f;
#pragma unroll
    for (int q = lane; q < CPBH; q += 32) s += hid[q] * w2h[q];
#pragma unroll
    for (int o = 16; o > 0; o >>= 1) s += __shfl_xor_sync(0xffffffffu, s, o);
    if (lane == 0) tbl[p * HEADS + warp] = s;
}

__global__ void bias_gather_kernel(const float* __restrict__ tbl,
                                   const int* __restrict__ rel_index,
                                   float* __restrict__ bias)
{
    int t = blockIdx.x * blockDim.x + threadIdx.x;
    const int TOT = HEADS * NTOK * NTOK;
    if (t >= TOT) return;
    int h  = t / (NTOK * NTOK);
    int ij = t % (NTOK * NTOK);
    float x = tbl[rel_index[ij] * HEADS + h];
    bias[(size_t)h * NTOK * NTOK + ij] = 16.f / (1.f + __expf(-x));
}

// =========================================================================
// Window attention v10: QK main term fp32-acc, correction terms fp16-acc
// (full-rate pipe). Interleaved q/k inputs, fp16 output.
// =========================================================================
#define KSTR_H 40
#define VSTR_H 152
#define PVSTR  18

#define AK_KHI 0
#define AK_KLO (AK_KHI + NTOK * KSTR_H * 2)
#define AK_VHI (AK_KLO + NTOK * KSTR_H * 2)
#define AK_PVB (AK_VHI + DHEAD * VSTR_H * 2)
#define AK_SUM (AK_PVB + 9 * 32 * PVSTR * 4)
#define ATTN_SMEM_BYTES (AK_SUM + 9 * 2 * 32 * 4)

__global__ __launch_bounds__(576, 1)
void attn_tc10_kernel(const uint2* __restrict__ qs,
                      const uint2* __restrict__ ks,
                      const __half* __restrict__ vh,
                      const float* __restrict__ bias,
                      const float* __restrict__ mask,
                      __half* __restrict__ outH)
{
    extern __shared__ __align__(16) char dsm[];

    const int h = blockIdx.x;
    const int b = blockIdx.y;
    const int w = b & (NW - 1);

    const int tid  = threadIdx.x;
    const int lane = tid & 31;
    const int warp = tid >> 5;
    const int pair = warp % 9;
    const int half = warp / 9;
    const int ng   = half ? 5 : 4;
    const int hbase = half ? 64 : 0;
    const int g  = lane >> 2;
    const int t  = lane & 3;
    const int R0 = pair * 16;

    const size_t rowB = (size_t)b * NTOK;
    const size_t hOff = (size_t)h * DHEAD;
    const size_t pOff = hOff >> 1;

    __half* knHi = (__half*)(dsm + AK_KHI);
    __half* knLo = (__half*)(dsm + AK_KLO);
    __half* vtHi = (__half*)(dsm + AK_VHI);
    float*  pvb  = (float*)(dsm + AK_PVB);
    float*  sumb = (float*)(dsm + AK_SUM);
    const uint32_t knHiB = s2u(knHi);
    const uint32_t knLoB = s2u(knLo);
    const uint32_t vtHiB = s2u(vtHi);

    // ---------- PHASE 0: front-batched loads ----------
    const int p16 = lane & 15, h16 = lane >> 4;
    uint2 khl[4];
#pragma unroll
    for (int i = 0; i < 4; i++) {
        int j = warp * 8 + 2 * i + h16;
        khl[i] = ks[(rowB + j) * (CDIM / 2) + pOff + p16];
    }
    __half vhr[8];
#pragma unroll
    for (int i = 0; i < 8; i++) {
        int j = warp * 8 + i;
        vhr[i] = vh[(rowB + j) * CDIM + hOff + lane];
    }
    uint32_t qah[2][4], qal[2][4];
    {
        const uint2* q0 = qs + (rowB + R0 + g) * (CDIM / 2) + pOff;
        const uint2* q1 = q0 + 8 * (CDIM / 2);
#pragma unroll
        for (int kc = 0; kc < 2; kc++) {
            uint2 u;
            u = q0[8 * kc + t];     qah[kc][0] = u.x; qal[kc][0] = u.y;
            u = q1[8 * kc + t];     qah[kc][1] = u.x; qal[kc][1] = u.y;
            u = q0[8 * kc + 4 + t]; qah[kc][2] = u.x; qal[kc][2] = u.y;
            u = q1[8 * kc + 4 + t]; qah[kc][3] = u.x; qal[kc][3] = u.y;
        }
    }
    float acc[10][4];
    {
        const float* biasR0 = bias + (size_t)h * NTOK * NTOK + (size_t)(R0 + g) * NTOK + hbase + 2 * t;
        const float* biasR1 = biasR0 + 8 * NTOK;
        const float* maskR0 = mask + (size_t)w * NTOK * NTOK + (size_t)(R0 + g) * NTOK + hbase + 2 * t;
        const float* maskR1 = maskR0 + 8 * NTOK;
#pragma unroll
        for (int nt = 0; nt < 10; nt++) {
            if (nt < 2 * ng) {
                float2 bb0 = *(const float2*)(biasR0 + 8 * nt);
                float2 mm0 = *(const float2*)(maskR0 + 8 * nt);
                float2 bb1 = *(const float2*)(biasR1 + 8 * nt);
                float2 mm1 = *(const float2*)(maskR1 + 8 * nt);
                acc[nt][0] = bb0.x + mm0.x;
                acc[nt][1] = bb0.y + mm0.y;
                acc[nt][2] = bb1.x + mm1.x;
                acc[nt][3] = bb1.y + mm1.y;
            } else {
#pragma unroll
                for (int c = 0; c < 4; c++) acc[nt][c] = 0.f;
            }
        }
    }

    // ---------- PHASE 1: stores to smem ----------
#pragma unroll
    for (int i = 0; i < 4; i++) {
        int j = warp * 8 + 2 * i + h16;
        *(uint32_t*)&knHi[j * KSTR_H + 2 * p16] = khl[i].x;
        *(uint32_t*)&knLo[j * KSTR_H + 2 * p16] = khl[i].y;
    }
#pragma unroll
    for (int i = 0; i < 8; i++) {
        int j = warp * 8 + i;
        vtHi[lane * VSTR_H + j] = vhr[i];
    }
    __syncthreads();

    // ---------- QK^T: main term fp32-acc, corrections fp16-acc ----------
    const uint32_t ldsmRow = (uint32_t)((lane & 7) + ((lane & 16) ? 8 : 0));
    const uint32_t ldsmCol = (uint32_t)((lane >> 3) & 1) * 16;

#pragma unroll
    for (int gI = 0; gI < 5; gI++) {
        if (gI < ng) {
            uint32_t c00 = 0, c01 = 0, c10 = 0, c11 = 0;   // fp16 correction accs
#pragma unroll
            for (int kc = 0; kc < 2; kc++) {
                uint32_t off = (uint32_t)(hbase + gI * 16 + ldsmRow) * (KSTR_H * 2)
                             + ldsmCol + (uint32_t)kc * 32;
                uint32_t bh0, bh1, bh2, bh3, bl0, bl1, bl2, bl3;
                LDSM_X4(bh0, bh1, bh2, bh3, knHiB + off);
                LDSM_X4(bl0, bl1, bl2, bl3, knLoB + off);
                MMA_F16(acc[2 * gI],     qah[kc][0], qah[kc][1], qah[kc][2], qah[kc][3], bh0, bh1);
                MMA_F16ACC(c00, c01,     qah[kc][0], qah[kc][1], qah[kc][2], qah[kc][3], bl0, bl1);
                MMA_F16ACC(c00, c01,     qal[kc][0], qal[kc][1], qal[kc][2], qal[kc][3], bh0, bh1);
                MMA_F16(acc[2 * gI + 1], qah[kc][0], qah[kc][1], qah[kc][2], qah[kc][3], bh2, bh3);
                MMA_F16ACC(c10, c11,     qah[kc][0], qah[kc][1], qah[kc][2], qah[kc][3], bl2, bl3);
                MMA_F16ACC(c10, c11,     qal[kc][0], qal[kc][1], qal[kc][2], qal[kc][3], bh2, bh3);
            }
            // unpack fp16 corrections into fp32 accumulators
            {
                __half2 hh;
                hh = *(__half2*)&c00;
                acc[2 * gI][0] += __low2float(hh);  acc[2 * gI][1] += __high2float(hh);
                hh = *(__half2*)&c01;
                acc[2 * gI][2] += __low2float(hh);  acc[2 * gI][3] += __high2float(hh);
                hh = *(__half2*)&c10;
                acc[2 * gI + 1][0] += __low2float(hh);  acc[2 * gI + 1][1] += __high2float(hh);
                hh = *(__half2*)&c11;
                acc[2 * gI + 1][2] += __low2float(hh);  acc[2 * gI + 1][3] += __high2float(hh);
            }
        }
    }

    // ---------- local max, exp, local sums ----------
    float mx0 = -1e30f, mx1 = -1e30f, sm0 = 0.f, sm1 = 0.f;
    {
#pragma unroll
        for (int nt = 0; nt < 10; nt++) {
            if (nt < 2 * ng) {
                mx0 = fmaxf(mx0, fmaxf(acc[nt][0], acc[nt][1]));
                mx1 = fmaxf(mx1, fmaxf(acc[nt][2], acc[nt][3]));
            }
        }
        mx0 = fmaxf(mx0, __shfl_xor_sync(0xffffffffu, mx0, 1));
        mx0 = fmaxf(mx0, __shfl_xor_sync(0xffffffffu, mx0, 2));
        mx1 = fmaxf(mx1, __shfl_xor_sync(0xffffffffu, mx1, 1));
        mx1 = fmaxf(mx1, __shfl_xor_sync(0xffffffffu, mx1, 2));
#pragma unroll
        for (int nt = 0; nt < 10; nt++) {
            if (nt < 2 * ng) {
                acc[nt][0] = __expf(acc[nt][0] - mx0);
                acc[nt][1] = __expf(acc[nt][1] - mx0);
                acc[nt][2] = __expf(acc[nt][2] - mx1);
                acc[nt][3] = __expf(acc[nt][3] - mx1);
                sm0 += acc[nt][0] + acc[nt][1];
                sm1 += acc[nt][2] + acc[nt][3];
            }
        }
        sm0 += __shfl_xor_sync(0xffffffffu, sm0, 1);
        sm0 += __shfl_xor_sync(0xffffffffu, sm0, 2);
        sm1 += __shfl_xor_sync(0xffffffffu, sm1, 1);
        sm1 += __shfl_xor_sync(0xffffffffu, sm1, 2);
        if (t == 0) {
            float* sb = sumb + (pair * 2 + half) * 32;
            sb[g]          = sm0;
            sb[g + 8]      = sm1;
            sb[16 + g]     = mx0;
            sb[16 + g + 8] = mx1;
        }
    }

    // ---------- PV (plain fp16 operands, fp32 acc) ----------
    float pv[4][4];
#pragma unroll
    for (int nt = 0; nt < 4; nt++)
#pragma unroll
        for (int c = 0; c < 4; c++) pv[nt][c] = 0.f;

#pragma unroll
    for (int kc2 = 0; kc2 < 5; kc2++) {
        if (kc2 < ng) {
            uint32_t ph[4];
            ph[0] = pack_h2(acc[2 * kc2][0],     acc[2 * kc2][1]);
            ph[1] = pack_h2(acc[2 * kc2][2],     acc[2 * kc2][3]);
            ph[2] = pack_h2(acc[2 * kc2 + 1][0], acc[2 * kc2 + 1][1]);
            ph[3] = pack_h2(acc[2 * kc2 + 1][2], acc[2 * kc2 + 1][3]);
            const uint32_t gk = (uint32_t)((hbase >> 4) + kc2);
#pragma unroll
            for (int p = 0; p < 2; p++) {
                uint32_t off = (uint32_t)(p * 16 + ldsmRow) * (VSTR_H * 2)
                             + ldsmCol + gk * 32;
                uint32_t bh0, bh1, bh2, bh3;
                LDSM_X4(bh0, bh1, bh2, bh3, vtHiB + off);
                MMA_F16(pv[2 * p],     ph[0], ph[1], ph[2], ph[3], bh0, bh1);
                MMA_F16(pv[2 * p + 1], ph[0], ph[1], ph[2], ph[3], bh2, bh3);
            }
        }
    }

    // ---------- pairwise combine + fp16 epilogue ----------
    if (half == 1) {
        float* pb = pvb + (pair * 32 + lane) * PVSTR;
#pragma unroll
        for (int nt = 0; nt < 4; nt++) {
            *(float2*)(pb + nt * 4)     = make_float2(pv[nt][0], pv[nt][1]);
            *(float2*)(pb + nt * 4 + 2) = make_float2(pv[nt][2], pv[nt][3]);
        }
    }
    __syncthreads();
    if (half == 0) {
        const float* sbO = sumb + (pair * 2 + 1) * 32;
        const float smO0 = sbO[g],      mxO0 = sbO[16 + g];
        const float smO1 = sbO[g + 8],  mxO1 = sbO[16 + g + 8];
        const float M0 = fmaxf(mx0, mxO0);
        const float M1 = fmaxf(mx1, mxO1);
        const float fl0 = __expf(mx0 - M0), fo0 = __expf(mxO0 - M0);
        const float fl1 = __expf(mx1 - M1), fo1 = __expf(mxO1 - M1);
        const float inv0 = 1.f / (sm0 * fl0 + smO0 * fo0);
        const float inv1 = 1.f / (sm1 * fl1 + smO1 * fo1);
        const float* pb = pvb + (pair * 32 + lane) * PVSTR;
        __half* o0 = outH + (rowB + R0 + g) * CDIM + hOff + 2 * t;
        __half* o1 = o0 + (size_t)8 * CDIM;
#pragma unroll
        for (int nt = 0; nt < 4; nt++) {
            float2 q0 = *(const float2*)(pb + nt * 4);
            float2 q1 = *(const float2*)(pb + nt * 4 + 2);
            *(uint32_t*)(o0 + 8 * nt) = pack_h2((pv[nt][0] * fl0 + q0.x * fo0) * inv0,
                                                (pv[nt][1] * fl0 + q0.y * fo0) * inv0);
            *(uint32_t*)(o1 + 8 * nt) = pack_h2((pv[nt][2] * fl1 + q1.x * fo1) * inv1,
                                                (pv[nt][3] * fl1 + q1.y * fo1) * inv1);
        }
    }
}

// =========================================================================
// launch
// =========================================================================
extern "C" void kernel_launch(void* const* d_in, const int* in_sizes, int n_in,
                              void* d_out, int out_size)
{
    const float* x           = (const float*)d_in[0];
    const float* mask        = (const float*)d_in[1];
    const float* qkv_w       = (const float*)d_in[2];
    const float* logit_scale = (const float*)d_in[3];
    const float* cpb_w1      = (const float*)d_in[4];
    const float* cpb_b1      = (const float*)d_in[5];
    const float* cpb_w2      = (const float*)d_in[6];
    const float* proj_w      = (const float*)d_in[7];
    const float* proj_b      = (const float*)d_in[8];
    const float* rel_table   = (const float*)d_in[9];
    const int*   rel_index   = (const int*)d_in[10];
    float* out = (float*)d_out;

    uint2 *qsP, *ksP;
    __half *vhP, *attH;
    float *tbl, *bias;
    cudaGetSymbolAddress((void**)&qsP,  g_qs);
    cudaGetSymbolAddress((void**)&ksP,  g_ks);
    cudaGetSymbolAddress((void**)&vhP,  g_vh);
    cudaGetSymbolAddress((void**)&attH, g_attH);
    cudaGetSymbolAddress((void**)&tbl,  g_tbl);
    cudaGetSymbolAddress((void**)&bias, g_bias);

    cudaFuncSetAttribute(gemm_qkv_fused,
                         cudaFuncAttributeMaxDynamicSharedMemorySize, GT_SMEM_BYTES);
    cudaFuncSetAttribute(gemm_proj,
                         cudaFuncAttributeMaxDynamicSharedMemorySize, GT_SMEM_BYTES);
    cudaFuncSetAttribute(attn_tc10_kernel,
                         cudaFuncAttributeMaxDynamicSharedMemorySize, ATTN_SMEM_BYTES);

    // 1) QKV projection + fused normalize/split epilogue
    {
        dim3 grid(QKVC / 256, MROWS / 128);
        gemm_qkv_fused<<<grid, 512, GT_SMEM_BYTES>>>(x, qkv_w, logit_scale,
                                                     qsP, ksP, vhP);
    }

    // 2) relative position bias table + gather
    cpb_tbl_kernel<<<NPOS, CPBH>>>(rel_table, cpb_w1, cpb_b1, cpb_w2, tbl);
    {
        int tot = HEADS * NTOK * NTOK;
        bias_gather_kernel<<<(tot + 255) / 256, 256>>>(tbl, rel_index, bias);
    }

    // 3) attention v10 (fp16-acc correction terms)
    {
        dim3 grid(HEADS, BWIN);
        attn_tc10_kernel<<<grid, 576, ATTN_SMEM_BYTES>>>(qsP, ksP, vhP,
                                                         bias, mask, attH);
    }

    // 4) output projection (fp16 A path)
    {
        dim3 grid(CDIM / 256, MROWS / 128);
        gemm_proj<<<grid, 512, GT_SMEM_BYTES>>>(attH, proj_w, proj_b, out);
    }
}

// round 17
// speedup vs baseline: 1.1370x; 1.0037x over previous
#include <cuda_runtime.h>
#include <cuda_bf16.h>
#include <cuda_fp16.h>
#include <math.h>
#include <stdint.h>

// ---------------- problem constants ----------------
#define BWIN   512
#define NTOK   144
#define CDIM   512
#define HEADS  16
#define DHEAD  32
#define NW     64
#define MROWS  (BWIN * NTOK)        // 73728
#define QKVC   (3 * CDIM)           // 1536
#define NPOS   (23 * 23)
#define CPBH   512

// ---------------- scratch ----------------
__device__ uint2  g_qs[(size_t)MROWS * (CDIM / 2)];
__device__ uint2  g_ks[(size_t)MROWS * (CDIM / 2)];
__device__ __half g_vh[(size_t)MROWS * CDIM];
__device__ __half g_attH[(size_t)MROWS * CDIM];
__device__ __half g_maskH[(size_t)NW * NTOK * NTOK];
__device__ float  g_tbl [NPOS * HEADS];
__device__ float  g_bias[(size_t)HEADS * NTOK * NTOK];

__device__ __forceinline__ uint32_t s2u(const void* p) {
    return (uint32_t)__cvta_generic_to_shared(p);
}
__device__ __forceinline__ uint2 f4_to_h4(float4 v) {
    __half2 h0 = __float22half2_rn(make_float2(v.x, v.y));
    __half2 h1 = __float22half2_rn(make_float2(v.z, v.w));
    uint2 u;
    u.x = *(uint32_t*)&h0;
    u.y = *(uint32_t*)&h1;
    return u;
}
__device__ __forceinline__ void split_pack(float x, float y, uint32_t& hi, uint32_t& lo) {
    __half hx = __float2half_rn(x), hy = __float2half_rn(y);
    __half2 h = __halves2half2(hx, hy);
    hi = *(uint32_t*)&h;
    __half2 l = __floats2half2_rn(x - __half2float(hx), y - __half2float(hy));
    lo = *(uint32_t*)&l;
}
__device__ __forceinline__ uint32_t pack_h2(float x, float y) {
    __half2 h = __floats2half2_rn(x, y);
    return *(uint32_t*)&h;
}

#define MMA_F16(d, a0,a1,a2,a3, b0,b1)                                         \
    asm volatile("mma.sync.aligned.m16n8k16.row.col.f32.f16.f16.f32 "          \
                 "{%0,%1,%2,%3},{%4,%5,%6,%7},{%8,%9},{%0,%1,%2,%3};"          \
                 : "+f"(d[0]), "+f"(d[1]), "+f"(d[2]), "+f"(d[3])              \
                 : "r"(a0), "r"(a1), "r"(a2), "r"(a3), "r"(b0), "r"(b1))

#define MMA_F16ACC(d0, d1, a0,a1,a2,a3, b0,b1)                                 \
    asm volatile("mma.sync.aligned.m16n8k16.row.col.f16.f16.f16.f16 "          \
                 "{%0,%1},{%2,%3,%4,%5},{%6,%7},{%0,%1};"                      \
                 : "+r"(d0), "+r"(d1)                                          \
                 : "r"(a0), "r"(a1), "r"(a2), "r"(a3), "r"(b0), "r"(b1))

#define LDSM_X4(r0,r1,r2,r3, addr)                                             \
    asm volatile("ldmatrix.sync.aligned.m8n8.x4.shared.b16 {%0,%1,%2,%3}, [%4];" \
                 : "=r"(r0), "=r"(r1), "=r"(r2), "=r"(r3) : "r"(addr))

// =========================================================================
// Shared GEMM config (proven mainloop)
// =========================================================================
#define GBK    32
#define GLDH   40
#define ABUFH  (128 * GLDH)
#define BBUFH  (256 * GLDH)
#define GT_SMEM_BYTES ((2 * ABUFH + 2 * BBUFH) * 2)   // 61440

#define GEMM_MAINLOOP_BODY(A_, B_, K_)                                          \
    extern __shared__ __align__(16) __half gsm[];                               \
    __half* As = gsm;                                                           \
    __half* Bs = gsm + 2 * ABUFH;                                               \
    const int tid  = threadIdx.x;                                               \
    const int lane = tid & 31;                                                  \
    const int warp = tid >> 5;                                                  \
    const int warpM = (warp & 3) * 32;                                          \
    const int warpN = (warp >> 2) * 64;                                         \
    const int rowBase = blockIdx.y * 128;                                       \
    const int colBase = blockIdx.x * 256;                                       \
    const int r  = tid >> 3;                                                    \
    const int kq = tid & 7;                                                     \
    const float* Ag = (A_) + (size_t)(rowBase + r) * (K_) + kq * 4;             \
    const float* Bg = (B_) + (size_t)(colBase + r) * (K_) + kq * 4;             \
    float4 ra[2], rb[4];                                                        \
    float acc[2][8][4];                                                         \
    _Pragma("unroll")                                                           \
    for (int mi = 0; mi < 2; mi++)                                              \
        _Pragma("unroll")                                                       \
        for (int ni = 0; ni < 8; ni++)                                          \
            _Pragma("unroll")                                                   \
            for (int c = 0; c < 4; c++) acc[mi][ni][c] = 0.f;                   \
    const uint32_t aOff = (uint32_t)((warpM + (lane & 7) + ((lane >> 3) & 1) * 8) * (GLDH * 2)) \
                        + (uint32_t)(lane >> 4) * 16;                           \
    const uint32_t bOff = (uint32_t)((warpN + (lane & 7) + ((lane & 16) ? 8 : 0)) * (GLDH * 2)) \
                        + (uint32_t)((lane >> 3) & 1) * 16;                     \
    const uint32_t asBase = s2u(As);                                            \
    const uint32_t bsBase = s2u(Bs);                                            \
    {                                                                           \
        const float* ap = Ag; const float* bp = Bg;                             \
        ra[0] = *(const float4*)(ap);                                           \
        ra[1] = *(const float4*)(ap + (size_t)64 * (K_));                       \
        rb[0] = *(const float4*)(bp);                                           \
        rb[1] = *(const float4*)(bp + (size_t)64 * (K_));                       \
        rb[2] = *(const float4*)(bp + (size_t)128 * (K_));                      \
        rb[3] = *(const float4*)(bp + (size_t)192 * (K_));                      \
        _Pragma("unroll")                                                       \
        for (int i = 0; i < 2; i++)                                             \
            *(uint2*)&As[(r + 64 * i) * GLDH + kq * 4] = f4_to_h4(ra[i]);       \
        _Pragma("unroll")                                                       \
        for (int i = 0; i < 4; i++)                                             \
            *(uint2*)&Bs[(r + 64 * i) * GLDH + kq * 4] = f4_to_h4(rb[i]);       \
    }                                                                           \
    __syncthreads();                                                            \
    const int NIT = (K_) / GBK;                                                 \
    for (int it = 0; it < NIT; ++it) {                                          \
        const int buf = it & 1;                                                 \
        if (it + 1 < NIT) {                                                     \
            const float* ap = Ag + (it + 1) * GBK;                              \
            const float* bp = Bg + (it + 1) * GBK;                              \
            ra[0] = *(const float4*)(ap);                                       \
            ra[1] = *(const float4*)(ap + (size_t)64 * (K_));                   \
            rb[0] = *(const float4*)(bp);                                       \
            rb[1] = *(const float4*)(bp + (size_t)64 * (K_));                   \
            rb[2] = *(const float4*)(bp + (size_t)128 * (K_));                  \
            rb[3] = *(const float4*)(bp + (size_t)192 * (K_));                  \
        }                                                                       \
        const uint32_t aB = asBase + (uint32_t)buf * (ABUFH * 2);               \
        const uint32_t bB = bsBase + (uint32_t)buf * (BBUFH * 2);               \
        _Pragma("unroll")                                                       \
        for (int kk = 0; kk < 2; kk++) {                                        \
            uint32_t a[2][4], bf[8][2];                                         \
            _Pragma("unroll")                                                   \
            for (int mi = 0; mi < 2; mi++) {                                    \
                uint32_t addr = aB + aOff + (uint32_t)(mi * 16 * GLDH * 2) + (uint32_t)(kk * 32); \
                LDSM_X4(a[mi][0], a[mi][1], a[mi][2], a[mi][3], addr);          \
            }                                                                   \
            _Pragma("unroll")                                                   \
            for (int p = 0; p < 4; p++) {                                       \
                uint32_t addr = bB + bOff + (uint32_t)(p * 16 * GLDH * 2) + (uint32_t)(kk * 32); \
                uint32_t r0, r1, r2, r3;                                        \
                LDSM_X4(r0, r1, r2, r3, addr);                                  \
                bf[2 * p][0] = r0; bf[2 * p][1] = r1;                           \
                bf[2 * p + 1][0] = r2; bf[2 * p + 1][1] = r3;                   \
            }                                                                   \
            _Pragma("unroll")                                                   \
            for (int mi = 0; mi < 2; mi++)                                      \
                _Pragma("unroll")                                               \
                for (int ni = 0; ni < 8; ni++)                                  \
                    MMA_F16(acc[mi][ni], a[mi][0], a[mi][1], a[mi][2], a[mi][3],\
                            bf[ni][0], bf[ni][1]);                              \
        }                                                                       \
        if (it + 1 < NIT) {                                                     \
            const int nb = buf ^ 1;                                             \
            _Pragma("unroll")                                                   \
            for (int i = 0; i < 2; i++)                                         \
                *(uint2*)&As[nb * ABUFH + (r + 64 * i) * GLDH + kq * 4] = f4_to_h4(ra[i]); \
            _Pragma("unroll")                                                   \
            for (int i = 0; i < 4; i++)                                         \
                *(uint2*)&Bs[nb * BBUFH + (r + 64 * i) * GLDH + kq * 4] = f4_to_h4(rb[i]); \
        }                                                                       \
        __syncthreads();                                                        \
    }

// =========================================================================
// QKV GEMM with fused normalize+split epilogue (unchanged from R15)
// =========================================================================
__global__ __launch_bounds__(512, 1)
void gemm_qkv_fused(const float* __restrict__ A,
                    const float* __restrict__ B,
                    const float* __restrict__ logit_scale,
                    uint2* __restrict__ qs, uint2* __restrict__ ks,
                    __half* __restrict__ vh)
{
    GEMM_MAINLOOP_BODY(A, B, CDIM)

    const int g  = lane >> 2;
    const int region = (colBase + warpN) >> 9;
    const int colLoc = (colBase + warpN) & 511;
    const int cq = (lane & 3) * 2;

    if (region == 2) {
#pragma unroll
        for (int mi = 0; mi < 2; mi++) {
            const size_t r0 = (size_t)(rowBase + warpM + mi * 16 + g);
#pragma unroll
            for (int ni = 0; ni < 8; ni++) {
                const int cl = colLoc + ni * 8 + cq;
                *(uint32_t*)&vh[r0 * CDIM + cl] =
                    pack_h2(acc[mi][ni][0], acc[mi][ni][1]);
                *(uint32_t*)&vh[(r0 + 8) * CDIM + cl] =
                    pack_h2(acc[mi][ni][2], acc[mi][ni][3]);
            }
        }
        return;
    }

    uint2* dst = (region == 0) ? qs : ks;
    float gscale[2] = {1.f, 1.f};
    if (region == 0) {
#pragma unroll
        for (int grp = 0; grp < 2; grp++) {
            int head = (colLoc >> 5) + grp;
            gscale[grp] = __expf(fminf(logit_scale[head], 4.60517018598809f));
        }
    }

#pragma unroll
    for (int mi = 0; mi < 2; mi++) {
        const size_t r0 = (size_t)(rowBase + warpM + mi * 16 + g);
#pragma unroll
        for (int grp = 0; grp < 2; grp++) {
            float s0 = 0.f, s1 = 0.f;
#pragma unroll
            for (int ni = 4 * grp; ni < 4 * grp + 4; ni++) {
                s0 += acc[mi][ni][0] * acc[mi][ni][0] + acc[mi][ni][1] * acc[mi][ni][1];
                s1 += acc[mi][ni][2] * acc[mi][ni][2] + acc[mi][ni][3] * acc[mi][ni][3];
            }
            s0 += __shfl_xor_sync(0xffffffffu, s0, 1);
            s0 += __shfl_xor_sync(0xffffffffu, s0, 2);
            s1 += __shfl_xor_sync(0xffffffffu, s1, 1);
            s1 += __shfl_xor_sync(0xffffffffu, s1, 2);
            float rn0 = rsqrtf(s0) * gscale[grp];
            float rn1 = rsqrtf(s1) * gscale[grp];
#pragma unroll
            for (int ni = 4 * grp; ni < 4 * grp + 4; ni++) {
                const int pr = (colLoc + ni * 8 + cq) >> 1;
                uint32_t hi, lo;
                split_pack(acc[mi][ni][0] * rn0, acc[mi][ni][1] * rn0, hi, lo);
                dst[r0 * (CDIM / 2) + pr] = make_uint2(hi, lo);
                split_pack(acc[mi][ni][2] * rn1, acc[mi][ni][3] * rn1, hi, lo);
                dst[(r0 + 8) * (CDIM / 2) + pr] = make_uint2(hi, lo);
            }
        }
    }
}

// =========================================================================
// Output projection (fp16 A path) — unchanged from R15
// =========================================================================
__global__ __launch_bounds__(512, 1)
void gemm_proj(const __half* __restrict__ A,
               const float* __restrict__ B,
               const float* __restrict__ bias,
               float* __restrict__ C)
{
    extern __shared__ __align__(16) __half gsm[];
    __half* As = gsm;
    __half* Bs = gsm + 2 * ABUFH;

    const int tid  = threadIdx.x;
    const int lane = tid & 31;
    const int warp = tid >> 5;
    const int warpM = (warp & 3) * 32;
    const int warpN = (warp >> 2) * 64;
    const int rowBase = blockIdx.y * 128;
    const int colBase = blockIdx.x * 256;

    const int r  = tid >> 3;
    const int kq = tid & 7;
    const __half* Ag = A + (size_t)(rowBase + r) * CDIM + kq * 4;
    const float*  Bg = B + (size_t)(colBase + r) * CDIM + kq * 4;

    uint2 ra[2];
    float4 rb[4];

    float acc[2][8][4];
#pragma unroll
    for (int mi = 0; mi < 2; mi++)
#pragma unroll
        for (int ni = 0; ni < 8; ni++)
#pragma unroll
            for (int c = 0; c < 4; c++) acc[mi][ni][c] = 0.f;

    const uint32_t aOff = (uint32_t)((warpM + (lane & 7) + ((lane >> 3) & 1) * 8) * (GLDH * 2))
                        + (uint32_t)(lane >> 4) * 16;
    const uint32_t bOff = (uint32_t)((warpN + (lane & 7) + ((lane & 16) ? 8 : 0)) * (GLDH * 2))
                        + (uint32_t)((lane >> 3) & 1) * 16;
    const uint32_t asBase = s2u(As);
    const uint32_t bsBase = s2u(Bs);

#define P_LOAD(it)  {                                                \
        const __half* ap = Ag + (it) * GBK;                          \
        const float*  bp = Bg + (it) * GBK;                          \
        ra[0] = *(const uint2*)(ap);                                 \
        ra[1] = *(const uint2*)(ap + (size_t)64 * CDIM);             \
        rb[0] = *(const float4*)(bp);                                \
        rb[1] = *(const float4*)(bp + (size_t)64 * CDIM);            \
        rb[2] = *(const float4*)(bp + (size_t)128 * CDIM);           \
        rb[3] = *(const float4*)(bp + (size_t)192 * CDIM);           \
    }
#define P_STS(buf)  {                                                           \
        _Pragma("unroll")                                                       \
        for (int i = 0; i < 2; i++)                                             \
            *(uint2*)&As[(buf) * ABUFH + (r + 64 * i) * GLDH + kq * 4] = ra[i]; \
        _Pragma("unroll")                                                       \
        for (int i = 0; i < 4; i++)                                             \
            *(uint2*)&Bs[(buf) * BBUFH + (r + 64 * i) * GLDH + kq * 4] = f4_to_h4(rb[i]); \
    }

    P_LOAD(0); P_STS(0); __syncthreads();

    const int NIT = CDIM / GBK;
    for (int it = 0; it < NIT; ++it) {
        const int buf = it & 1;
        if (it + 1 < NIT) P_LOAD(it + 1);

        const uint32_t aB = asBase + (uint32_t)buf * (ABUFH * 2);
        const uint32_t bB = bsBase + (uint32_t)buf * (BBUFH * 2);

#pragma unroll
        for (int kk = 0; kk < 2; kk++) {
            uint32_t a[2][4], bf[8][2];
#pragma unroll
            for (int mi = 0; mi < 2; mi++) {
                uint32_t addr = aB + aOff + (uint32_t)(mi * 16 * GLDH * 2) + (uint32_t)(kk * 32);
                LDSM_X4(a[mi][0], a[mi][1], a[mi][2], a[mi][3], addr);
            }
#pragma unroll
            for (int p = 0; p < 4; p++) {
                uint32_t addr = bB + bOff + (uint32_t)(p * 16 * GLDH * 2) + (uint32_t)(kk * 32);
                uint32_t r0, r1, r2, r3;
                LDSM_X4(r0, r1, r2, r3, addr);
                bf[2 * p][0] = r0; bf[2 * p][1] = r1;
                bf[2 * p + 1][0] = r2; bf[2 * p + 1][1] = r3;
            }
#pragma unroll
            for (int mi = 0; mi < 2; mi++)
#pragma unroll
                for (int ni = 0; ni < 8; ni++)
                    MMA_F16(acc[mi][ni], a[mi][0], a[mi][1], a[mi][2], a[mi][3],
                            bf[ni][0], bf[ni][1]);
        }
        if (it + 1 < NIT) P_STS(buf ^ 1);
        __syncthreads();
    }

    const int g  = lane >> 2;
    const int cq = (lane & 3) * 2;
#pragma unroll
    for (int mi = 0; mi < 2; mi++) {
        const int row0 = rowBase + warpM + mi * 16 + g;
#pragma unroll
        for (int ni = 0; ni < 8; ni++) {
            const int col = colBase + warpN + ni * 8 + cq;
            float b0 = bias[col], b1 = bias[col + 1];
            *(float2*)&C[(size_t)row0 * CDIM + col] =
                make_float2(acc[mi][ni][0] + b0, acc[mi][ni][1] + b1);
            *(float2*)&C[(size_t)(row0 + 8) * CDIM + col] =
                make_float2(acc[mi][ni][2] + b0, acc[mi][ni][3] + b1);
        }
    }
#undef P_LOAD
#undef P_STS
}

// =========================================================================
// CPB MLP table + bias gather + mask fp16 convert (tiny kernels)
// =========================================================================
__global__ __launch_bounds__(512)
void cpb_tbl_kernel(const float* __restrict__ rel_table,
                    const float* __restrict__ w1,
                    const float* __restrict__ b1,
                    const float* __restrict__ w2,
                    float* __restrict__ tbl)
{
    __shared__ float hid[CPBH];
    int p = blockIdx.x;
    float t0 = rel_table[2 * p], t1 = rel_table[2 * p + 1];
    int j = threadIdx.x;
    hid[j] = fmaxf(t0 * w1[2 * j] + t1 * w1[2 * j + 1] + b1[j], 0.f);
    __syncthreads();

    int warp = j >> 5, lane = j & 31;
    const float* w2h = w2 + warp * CPBH;
    float s = 0.f;
#pragma unroll
    for (int q = lane; q < CPBH; q += 32) s += hid[q] * w2h[q];
#pragma unroll
    for (int o = 16; o > 0; o >>= 1) s += __shfl_xor_sync(0xffffffffu, s, o);
    if (lane == 0) tbl[p * HEADS + warp] = s;
}

__global__ void bias_gather_kernel(const float* __restrict__ tbl,
                                   const int* __restrict__ rel_index,
                                   float* __restrict__ bias)
{
    int t = blockIdx.x * blockDim.x + threadIdx.x;
    const int TOT = HEADS * NTOK * NTOK;
    if (t >= TOT) return;
    int h  = t / (NTOK * NTOK);
    int ij = t % (NTOK * NTOK);
    float x = tbl[rel_index[ij] * HEADS + h];
    bias[(size_t)h * NTOK * NTOK + ij] = 16.f / (1.f + __expf(-x));
}

__global__ void mask_h_kernel(const float* __restrict__ mask,
                              __half* __restrict__ maskH)
{
    int t = blockIdx.x * blockDim.x + threadIdx.x;
    const int TOT = NW * NTOK * NTOK;
    if (t * 2 >= TOT) return;
    float2 v = *(const float2*)(mask + 2 * t);
    *(uint32_t*)(maskH + 2 * t) = pack_h2(v.x, v.y);
}

// =========================================================================
// Window attention v11: conflict-free packed V^T store (VSTR_H=168),
// fp16 mask. Otherwise = v10.
// =========================================================================
#define KSTR_H 40
#define VSTR_H 168                 // 336B stride: 84w; 84*r mod 32 distinct for r0..7
#define PVSTR  18

#define AK_KHI 0
#define AK_KLO (AK_KHI + NTOK * KSTR_H * 2)          // 11520
#define AK_VHI (AK_KLO + NTOK * KSTR_H * 2)          // 23040 (16B aligned)
#define AK_PVB (AK_VHI + DHEAD * VSTR_H * 2)         // 33792
#define AK_SUM (AK_PVB + 9 * 32 * PVSTR * 4)         // 54528
#define ATTN_SMEM_BYTES (AK_SUM + 9 * 2 * 32 * 4)    // 56832

__global__ __launch_bounds__(576, 1)
void attn_tc11_kernel(const uint2* __restrict__ qs,
                      const uint2* __restrict__ ks,
                      const __half* __restrict__ vh,
                      const float* __restrict__ bias,
                      const __half* __restrict__ maskH,
                      __half* __restrict__ outH)
{
    extern __shared__ __align__(16) char dsm[];

    const int h = blockIdx.x;
    const int b = blockIdx.y;
    const int w = b & (NW - 1);

    const int tid  = threadIdx.x;
    const int lane = tid & 31;
    const int warp = tid >> 5;
    const int pair = warp % 9;
    const int half = warp / 9;
    const int ng   = half ? 5 : 4;
    const int hbase = half ? 64 : 0;
    const int g  = lane >> 2;
    const int t  = lane & 3;
    const int R0 = pair * 16;

    const size_t rowB = (size_t)b * NTOK;
    const size_t hOff = (size_t)h * DHEAD;
    const size_t pOff = hOff >> 1;

    __half* knHi = (__half*)(dsm + AK_KHI);
    __half* knLo = (__half*)(dsm + AK_KLO);
    __half* vtHi = (__half*)(dsm + AK_VHI);
    float*  pvb  = (float*)(dsm + AK_PVB);
    float*  sumb = (float*)(dsm + AK_SUM);
    const uint32_t knHiB = s2u(knHi);
    const uint32_t knLoB = s2u(knLo);
    const uint32_t vtHiB = s2u(vtHi);

    // ---------- PHASE 0: front-batched loads ----------
    const int p16 = lane & 15, h16 = lane >> 4;
    uint2 khl[4];
#pragma unroll
    for (int i = 0; i < 4; i++) {
        int j = warp * 8 + 2 * i + h16;
        khl[i] = ks[(rowB + j) * (CDIM / 2) + pOff + p16];
    }
    // V: lane already holds V^T[lane][8w..8w+7] after these 8 loads
    __half vhr[8];
#pragma unroll
    for (int i = 0; i < 8; i++) {
        int j = warp * 8 + i;
        vhr[i] = vh[(rowB + j) * CDIM + hOff + lane];
    }
    uint32_t qah[2][4], qal[2][4];
    {
        const uint2* q0 = qs + (rowB + R0 + g) * (CDIM / 2) + pOff;
        const uint2* q1 = q0 + 8 * (CDIM / 2);
#pragma unroll
        for (int kc = 0; kc < 2; kc++) {
            uint2 u;
            u = q0[8 * kc + t];     qah[kc][0] = u.x; qal[kc][0] = u.y;
            u = q1[8 * kc + t];     qah[kc][1] = u.x; qal[kc][1] = u.y;
            u = q0[8 * kc + 4 + t]; qah[kc][2] = u.x; qal[kc][2] = u.y;
            u = q1[8 * kc + 4 + t]; qah[kc][3] = u.x; qal[kc][3] = u.y;
        }
    }
    float acc[10][4];
    {
        const float*  biasR0 = bias  + (size_t)h * NTOK * NTOK + (size_t)(R0 + g) * NTOK + hbase + 2 * t;
        const float*  biasR1 = biasR0 + 8 * NTOK;
        const __half* maskR0 = maskH + (size_t)w * NTOK * NTOK + (size_t)(R0 + g) * NTOK + hbase + 2 * t;
        const __half* maskR1 = maskR0 + 8 * NTOK;
#pragma unroll
        for (int nt = 0; nt < 10; nt++) {
            if (nt < 2 * ng) {
                float2 bb0 = *(const float2*)(biasR0 + 8 * nt);
                float2 bb1 = *(const float2*)(biasR1 + 8 * nt);
                float2 mm0 = __half22float2(*(const __half2*)(maskR0 + 8 * nt));
                float2 mm1 = __half22float2(*(const __half2*)(maskR1 + 8 * nt));
                acc[nt][0] = bb0.x + mm0.x;
                acc[nt][1] = bb0.y + mm0.y;
                acc[nt][2] = bb1.x + mm1.x;
                acc[nt][3] = bb1.y + mm1.y;
            } else {
#pragma unroll
                for (int c = 0; c < 4; c++) acc[nt][c] = 0.f;
            }
        }
    }

    // ---------- PHASE 1: stores to smem ----------
#pragma unroll
    for (int i = 0; i < 4; i++) {
        int j = warp * 8 + 2 * i + h16;
        *(uint32_t*)&knHi[j * KSTR_H + 2 * p16] = khl[i].x;
        *(uint32_t*)&knLo[j * KSTR_H + 2 * p16] = khl[i].y;
    }
    // packed conflict-free V^T store: one STS.128 per lane
    {
        uint4 vq;
        __half2 hh;
        hh = __halves2half2(vhr[0], vhr[1]); vq.x = *(uint32_t*)&hh;
        hh = __halves2half2(vhr[2], vhr[3]); vq.y = *(uint32_t*)&hh;
        hh = __halves2half2(vhr[4], vhr[5]); vq.z = *(uint32_t*)&hh;
        hh = __halves2half2(vhr[6], vhr[7]); vq.w = *(uint32_t*)&hh;
        *(uint4*)&vtHi[lane * VSTR_H + warp * 8] = vq;
    }
    __syncthreads();

    // ---------- QK^T: main fp32-acc + corrections fp16-acc ----------
    const uint32_t ldsmRow = (uint32_t)((lane & 7) + ((lane & 16) ? 8 : 0));
    const uint32_t ldsmCol = (uint32_t)((lane >> 3) & 1) * 16;

#pragma unroll
    for (int gI = 0; gI < 5; gI++) {
        if (gI < ng) {
            uint32_t c00 = 0, c01 = 0, c10 = 0, c11 = 0;
#pragma unroll
            for (int kc = 0; kc < 2; kc++) {
                uint32_t off = (uint32_t)(hbase + gI * 16 + ldsmRow) * (KSTR_H * 2)
                             + ldsmCol + (uint32_t)kc * 32;
                uint32_t bh0, bh1, bh2, bh3, bl0, bl1, bl2, bl3;
                LDSM_X4(bh0, bh1, bh2, bh3, knHiB + off);
                LDSM_X4(bl0, bl1, bl2, bl3, knLoB + off);
                MMA_F16(acc[2 * gI],     qah[kc][0], qah[kc][1], qah[kc][2], qah[kc][3], bh0, bh1);
                MMA_F16ACC(c00, c01,     qah[kc][0], qah[kc][1], qah[kc][2], qah[kc][3], bl0, bl1);
                MMA_F16ACC(c00, c01,     qal[kc][0], qal[kc][1], qal[kc][2], qal[kc][3], bh0, bh1);
                MMA_F16(acc[2 * gI + 1], qah[kc][0], qah[kc][1], qah[kc][2], qah[kc][3], bh2, bh3);
                MMA_F16ACC(c10, c11,     qah[kc][0], qah[kc][1], qah[kc][2], qah[kc][3], bl2, bl3);
                MMA_F16ACC(c10, c11,     qal[kc][0], qal[kc][1], qal[kc][2], qal[kc][3], bh2, bh3);
            }
            {
                __half2 hh;
                hh = *(__half2*)&c00;
                acc[2 * gI][0] += __low2float(hh);  acc[2 * gI][1] += __high2float(hh);
                hh = *(__half2*)&c01;
                acc[2 * gI][2] += __low2float(hh);  acc[2 * gI][3] += __high2float(hh);
                hh = *(__half2*)&c10;
                acc[2 * gI + 1][0] += __low2float(hh);  acc[2 * gI + 1][1] += __high2float(hh);
                hh = *(__half2*)&c11;
                acc[2 * gI + 1][2] += __low2float(hh);  acc[2 * gI + 1][3] += __high2float(hh);
            }
        }
    }

    // ---------- local max, exp, local sums ----------
    float mx0 = -1e30f, mx1 = -1e30f, sm0 = 0.f, sm1 = 0.f;
    {
#pragma unroll
        for (int nt = 0; nt < 10; nt++) {
            if (nt < 2 * ng) {
                mx0 = fmaxf(mx0, fmaxf(acc[nt][0], acc[nt][1]));
                mx1 = fmaxf(mx1, fmaxf(acc[nt][2], acc[nt][3]));
            }
        }
        mx0 = fmaxf(mx0, __shfl_xor_sync(0xffffffffu, mx0, 1));
        mx0 = fmaxf(mx0, __shfl_xor_sync(0xffffffffu, mx0, 2));
        mx1 = fmaxf(mx1, __shfl_xor_sync(0xffffffffu, mx1, 1));
        mx1 = fmaxf(mx1, __shfl_xor_sync(0xffffffffu, mx1, 2));
#pragma unroll
        for (int nt = 0; nt < 10; nt++) {
            if (nt < 2 * ng) {
                acc[nt][0] = __expf(acc[nt][0] - mx0);
                acc[nt][1] = __expf(acc[nt][1] - mx0);
                acc[nt][2] = __expf(acc[nt][2] - mx1);
                acc[nt][3] = __expf(acc[nt][3] - mx1);
                sm0 += acc[nt][0] + acc[nt][1];
                sm1 += acc[nt][2] + acc[nt][3];
            }
        }
        sm0 += __shfl_xor_sync(0xffffffffu, sm0, 1);
        sm0 += __shfl_xor_sync(0xffffffffu, sm0, 2);
        sm1 += __shfl_xor_sync(0xffffffffu, sm1, 1);
        sm1 += __shfl_xor_sync(0xffffffffu, sm1, 2);
        if (t == 0) {
            float* sb = sumb + (pair * 2 + half) * 32;
            sb[g]          = sm0;
            sb[g + 8]      = sm1;
            sb[16 + g]     = mx0;
            sb[16 + g + 8] = mx1;
        }
    }

    // ---------- PV (plain fp16 operands, fp32 acc) ----------
    float pv[4][4];
#pragma unroll
    for (int nt = 0; nt < 4; nt++)
#pragma unroll
        for (int c = 0; c < 4; c++) pv[nt][c] = 0.f;

#pragma unroll
    for (int kc2 = 0; kc2 < 5; kc2++) {
        if (kc2 < ng) {
            uint32_t ph[4];
            ph[0] = pack_h2(acc[2 * kc2][0],     acc[2 * kc2][1]);
            ph[1] = pack_h2(acc[2 * kc2][2],     acc[2 * kc2][3]);
            ph[2] = pack_h2(acc[2 * kc2 + 1][0], acc[2 * kc2 + 1][1]);
            ph[3] = pack_h2(acc[2 * kc2 + 1][2], acc[2 * kc2 + 1][3]);
            const uint32_t gk = (uint32_t)((hbase >> 4) + kc2);
#pragma unroll
            for (int p = 0; p < 2; p++) {
                uint32_t off = (uint32_t)(p * 16 + ldsmRow) * (VSTR_H * 2)
                             + ldsmCol + gk * 32;
                uint32_t bh0, bh1, bh2, bh3;
                LDSM_X4(bh0, bh1, bh2, bh3, vtHiB + off);
                MMA_F16(pv[2 * p],     ph[0], ph[1], ph[2], ph[3], bh0, bh1);
                MMA_F16(pv[2 * p + 1], ph[0], ph[1], ph[2], ph[3], bh2, bh3);
            }
        }
    }

    // ---------- pairwise combine + fp16 epilogue ----------
    if (half == 1) {
        float* pb = pvb + (pair * 32 + lane) * PVSTR;
#pragma unroll
        for (int nt = 0; nt < 4; nt++) {
            *(float2*)(pb + nt * 4)     = make_float2(pv[nt][0], pv[nt][1]);
            *(float2*)(pb + nt * 4 + 2) = make_float2(pv[nt][2], pv[nt][3]);
        }
    }
    __syncthreads();
    if (half == 0) {
        const float* sbO = sumb + (pair * 2 + 1) * 32;
        const float smO0 = sbO[g],      mxO0 = sbO[16 + g];
        const float smO1 = sbO[g + 8],  mxO1 = sbO[16 + g + 8];
        const float M0 = fmaxf(mx0, mxO0);
        const float M1 = fmaxf(mx1, mxO1);
        const float fl0 = __expf(mx0 - M0), fo0 = __expf(mxO0 - M0);
        const float fl1 = __expf(mx1 - M1), fo1 = __expf(mxO1 - M1);
        const float inv0 = 1.f / (sm0 * fl0 + smO0 * fo0);
        const float inv1 = 1.f / (sm1 * fl1 + smO1 * fo1);
        const float* pb = pvb + (pair * 32 + lane) * PVSTR;
        __half* o0 = outH + (rowB + R0 + g) * CDIM + hOff + 2 * t;
        __half* o1 = o0 + (size_t)8 * CDIM;
#pragma unroll
        for (int nt = 0; nt < 4; nt++) {
            float2 q0 = *(const float2*)(pb + nt * 4);
            float2 q1 = *(const float2*)(pb + nt * 4 + 2);
            *(uint32_t*)(o0 + 8 * nt) = pack_h2((pv[nt][0] * fl0 + q0.x * fo0) * inv0,
                                                (pv[nt][1] * fl0 + q0.y * fo0) * inv0);
            *(uint32_t*)(o1 + 8 * nt) = pack_h2((pv[nt][2] * fl1 + q1.x * fo1) * inv1,
                                                (pv[nt][3] * fl1 + q1.y * fo1) * inv1);
        }
    }
}

// =========================================================================
// launch
// =========================================================================
extern "C" void kernel_launch(void* const* d_in, const int* in_sizes, int n_in,
                              void* d_out, int out_size)
{
    const float* x           = (const float*)d_in[0];
    const float* mask        = (const float*)d_in[1];
    const float* qkv_w       = (const float*)d_in[2];
    const float* logit_scale = (const float*)d_in[3];
    const float* cpb_w1      = (const float*)d_in[4];
    const float* cpb_b1      = (const float*)d_in[5];
    const float* cpb_w2      = (const float*)d_in[6];
    const float* proj_w      = (const float*)d_in[7];
    const float* proj_b      = (const float*)d_in[8];
    const float* rel_table   = (const float*)d_in[9];
    const int*   rel_index   = (const int*)d_in[10];
    float* out = (float*)d_out;

    uint2 *qsP, *ksP;
    __half *vhP, *attH, *maskHP;
    float *tbl, *bias;
    cudaGetSymbolAddress((void**)&qsP,   g_qs);
    cudaGetSymbolAddress((void**)&ksP,   g_ks);
    cudaGetSymbolAddress((void**)&vhP,   g_vh);
    cudaGetSymbolAddress((void**)&attH,  g_attH);
    cudaGetSymbolAddress((void**)&maskHP, g_maskH);
    cudaGetSymbolAddress((void**)&tbl,   g_tbl);
    cudaGetSymbolAddress((void**)&bias,  g_bias);

    cudaFuncSetAttribute(gemm_qkv_fused,
                         cudaFuncAttributeMaxDynamicSharedMemorySize, GT_SMEM_BYTES);
    cudaFuncSetAttribute(gemm_proj,
                         cudaFuncAttributeMaxDynamicSharedMemorySize, GT_SMEM_BYTES);
    cudaFuncSetAttribute(attn_tc11_kernel,
                         cudaFuncAttributeMaxDynamicSharedMemorySize, ATTN_SMEM_BYTES);

    // 1) QKV projection + fused normalize/split epilogue
    {
        dim3 grid(QKVC / 256, MROWS / 128);
        gemm_qkv_fused<<<grid, 512, GT_SMEM_BYTES>>>(x, qkv_w, logit_scale,
                                                     qsP, ksP, vhP);
    }

    // 2) relative position bias table + gather + fp16 mask
    cpb_tbl_kernel<<<NPOS, CPBH>>>(rel_table, cpb_w1, cpb_b1, cpb_w2, tbl);
    {
        int tot = HEADS * NTOK * NTOK;
        bias_gather_kernel<<<(tot + 255) / 256, 256>>>(tbl, rel_index, bias);
        int totm = NW * NTOK * NTOK / 2;
        mask_h_kernel<<<(totm + 255) / 256, 256>>>(mask, maskHP);
    }

    // 3) attention v11 (conflict-free V^T store, fp16 mask)
    {
        dim3 grid(HEADS, BWIN);
        attn_tc11_kernel<<<grid, 576, ATTN_SMEM_BYTES>>>(qsP, ksP, vhP,
                                                         bias, maskHP, attH);
    }

    // 4) output projection (fp16 A path)
    {
        dim3 grid(CDIM / 256, MROWS / 128);
        gemm_proj<<<grid, 512, GT_SMEM_BYTES>>>(attH, proj_w, proj_b, out);
    }
}